// round 1
// baseline (speedup 1.0000x reference)
#include <cuda_runtime.h>

#define BB 2
#define SS 2048
#define DD 512
#define HH 8
#define DKK 64

// Scratch (static device globals: allocation-free per harness rules)
__device__ float g_Q[BB*SS*DD];
__device__ float g_K[BB*SS*DD];
__device__ float g_V[BB*SS*DD];
__device__ float g_Hc[BB*SS*DD];
__device__ int   g_len[2*BB];   // [rowlen[0..B), collen[0..B)]

// ---------------------------------------------------------------------------
// Mask length reduction: row_len[b] = sum_s row_pad_mask[b,s], same for col.
// ---------------------------------------------------------------------------
__global__ void masklen_kernel(const int* __restrict__ rm, const int* __restrict__ cm) {
    __shared__ int sr[256], sc[256];
    int b = blockIdx.x, t = threadIdx.x;
    int r = 0, c = 0;
    for (int s = t; s < SS; s += 256) { r += rm[b*SS + s]; c += cm[b*SS + s]; }
    sr[t] = r; sc[t] = c;
    __syncthreads();
    for (int o = 128; o > 0; o >>= 1) {
        if (t < o) { sr[t] += sr[t+o]; sc[t] += sc[t+o]; }
        __syncthreads();
    }
    if (t == 0) { g_len[b] = sr[0]; g_len[BB + b] = sc[0]; }
}

// ---------------------------------------------------------------------------
// Tiled GEMM body: C[64x64 tile] = A[M,K] @ W[N,K]^T + bias   (torch Linear)
// 256 threads, 4x4 micro-tile per thread, rows ty+16i / cols tx+16j.
// ---------------------------------------------------------------------------
__device__ __forceinline__ void gemm64(const float* __restrict__ A,
                                       const float* __restrict__ W,
                                       const float* __restrict__ bias,
                                       float* __restrict__ C,
                                       float* As, float* Ws,
                                       int K, int N, int bm, int bn) {
    int tid = threadIdx.x;
    int ty = tid >> 4, tx = tid & 15;
    float acc[4][4];
#pragma unroll
    for (int i = 0; i < 4; i++)
#pragma unroll
        for (int j = 0; j < 4; j++) acc[i][j] = 0.f;

    for (int k0 = 0; k0 < K; k0 += 32) {
#pragma unroll
        for (int i = 0; i < 2; i++) {
            int e = tid + i*256;
            int r = e >> 3;
            int c = (e & 7) << 2;
            float4 va = *(const float4*)(A + (size_t)(bm + r)*K + k0 + c);
            As[r*33 + c]   = va.x; As[r*33 + c+1] = va.y;
            As[r*33 + c+2] = va.z; As[r*33 + c+3] = va.w;
            float4 vw = *(const float4*)(W + (size_t)(bn + r)*K + k0 + c);
            Ws[r*33 + c]   = vw.x; Ws[r*33 + c+1] = vw.y;
            Ws[r*33 + c+2] = vw.z; Ws[r*33 + c+3] = vw.w;
        }
        __syncthreads();
#pragma unroll
        for (int kk = 0; kk < 32; kk++) {
            float a[4], w[4];
#pragma unroll
            for (int i = 0; i < 4; i++) a[i] = As[(ty + 16*i)*33 + kk];
#pragma unroll
            for (int j = 0; j < 4; j++) w[j] = Ws[(tx + 16*j)*33 + kk];
#pragma unroll
            for (int i = 0; i < 4; i++)
#pragma unroll
                for (int j = 0; j < 4; j++) acc[i][j] += a[i]*w[j];
        }
        __syncthreads();
    }
#pragma unroll
    for (int i = 0; i < 4; i++) {
        int m = bm + ty + 16*i;
#pragma unroll
        for (int j = 0; j < 4; j++) {
            int n = bn + tx + 16*j;
            C[(size_t)m*N + n] = acc[i][j] + bias[n];
        }
    }
}

// Fused Q/K/V projections: grid (M/64, N/64, 3)
__global__ void qkv_kernel(const float* __restrict__ inQ, const float* __restrict__ inK,
                           const float* __restrict__ inV,
                           const float* __restrict__ WQ, const float* __restrict__ bQ,
                           const float* __restrict__ WK, const float* __restrict__ bK,
                           const float* __restrict__ WV, const float* __restrict__ bV) {
    __shared__ float As[64*33], Ws[64*33];
    const float *A, *W, *bi;
    float* C;
    int z = blockIdx.z;
    if (z == 0)      { A = inQ; W = WQ; bi = bQ; C = g_Q; }
    else if (z == 1) { A = inK; W = WK; bi = bK; C = g_K; }
    else             { A = inV; W = WV; bi = bV; C = g_V; }
    gemm64(A, W, bi, C, As, Ws, DD, DD, blockIdx.x*64, blockIdx.y*64);
}

// Output projection: out = g_Hc @ W_O^T + b_O
__global__ void oproj_kernel(const float* __restrict__ WO, const float* __restrict__ bO,
                             float* __restrict__ out) {
    __shared__ float As[64*33], Ws[64*33];
    gemm64(g_Hc, WO, bO, out, As, Ws, DD, DD, blockIdx.x*64, blockIdx.y*64);
}

// ---------------------------------------------------------------------------
// Flash attention: one block per (b,h, 64-row q-tile), online softmax.
// Dynamic smem: Qs(64x65) Ks(64x65) Vs(64x64) Ps(64x65) = 66304 B.
// ---------------------------------------------------------------------------
__global__ void attn_kernel() {
    extern __shared__ float sm[];
    float* Qs = sm;                       // stride 65
    float* Ks = sm + 64*65;               // stride 65
    float* Vs = sm + 2*64*65;             // stride 64
    float* Ps = sm + 2*64*65 + 64*64;     // stride 65

    int bh = blockIdx.z;
    int b = bh >> 3, h = bh & 7;
    int qt = (int)gridDim.y - 1 - (int)blockIdx.y;   // heavy tiles first
    int qbase = qt << 6;
    int rowlen = g_len[b], collen = g_len[BB + b];
    int tid = threadIdx.x, ty = tid >> 4, tx = tid & 15;

    const float* Qp = g_Q + (size_t)b*SS*DD + h*DKK;
    const float* Kp = g_K + (size_t)b*SS*DD + h*DKK;
    const float* Vp = g_V + (size_t)b*SS*DD + h*DKK;

    // load Q tile [64 x 64]
#pragma unroll
    for (int i = 0; i < 4; i++) {
        int e = tid + i*256;
        int r = e >> 4, c = (e & 15) << 2;
        float4 v = *(const float4*)(Qp + (size_t)(qbase + r)*DD + c);
        Qs[r*65 + c]   = v.x; Qs[r*65 + c+1] = v.y;
        Qs[r*65 + c+2] = v.z; Qs[r*65 + c+3] = v.w;
    }

    float m[4], l[4], o[4][4];
#pragma unroll
    for (int i = 0; i < 4; i++) {
        m[i] = -1e30f; l[i] = 0.f;
#pragma unroll
        for (int j = 0; j < 4; j++) o[i][j] = 0.f;
    }

    int kmax = min(qbase + 64, collen);
    int nk = (kmax > 0) ? ((kmax + 63) >> 6) : 0;

    for (int kt = 0; kt < nk; kt++) {
        int kbase = kt << 6;
        // load K and V tiles
#pragma unroll
        for (int i = 0; i < 4; i++) {
            int e = tid + i*256;
            int r = e >> 4, c = (e & 15) << 2;
            float4 vk = *(const float4*)(Kp + (size_t)(kbase + r)*DD + c);
            Ks[r*65 + c]   = vk.x; Ks[r*65 + c+1] = vk.y;
            Ks[r*65 + c+2] = vk.z; Ks[r*65 + c+3] = vk.w;
            float4 vv = *(const float4*)(Vp + (size_t)(kbase + r)*DD + c);
            Vs[r*64 + c]   = vv.x; Vs[r*64 + c+1] = vv.y;
            Vs[r*64 + c+2] = vv.z; Vs[r*64 + c+3] = vv.w;
        }
        __syncthreads();

        // scores S = Q K^T
        float s[4][4];
#pragma unroll
        for (int i = 0; i < 4; i++)
#pragma unroll
            for (int j = 0; j < 4; j++) s[i][j] = 0.f;
#pragma unroll 8
        for (int d = 0; d < 64; d++) {
            float a[4], k4[4];
#pragma unroll
            for (int i = 0; i < 4; i++) a[i]  = Qs[(ty + 16*i)*65 + d];
#pragma unroll
            for (int j = 0; j < 4; j++) k4[j] = Ks[(tx + 16*j)*65 + d];
#pragma unroll
            for (int i = 0; i < 4; i++)
#pragma unroll
                for (int j = 0; j < 4; j++) s[i][j] += a[i]*k4[j];
        }
        // scale + causal/padding mask (sentinel -1e30)
#pragma unroll
        for (int i = 0; i < 4; i++) {
            int q = qbase + ty + 16*i;
#pragma unroll
            for (int j = 0; j < 4; j++) {
                int k = kbase + tx + 16*j;
                bool valid = (k <= q) && (q < rowlen) && (k < collen);
                s[i][j] = valid ? s[i][j]*0.125f : -1e30f;
            }
        }
        // row max across the 16-lane column group
        float mt[4];
#pragma unroll
        for (int i = 0; i < 4; i++)
            mt[i] = fmaxf(fmaxf(s[i][0], s[i][1]), fmaxf(s[i][2], s[i][3]));
#pragma unroll
        for (int off = 8; off > 0; off >>= 1)
#pragma unroll
            for (int i = 0; i < 4; i++)
                mt[i] = fmaxf(mt[i], __shfl_xor_sync(0xffffffffu, mt[i], off, 16));

        float rs[4];
#pragma unroll
        for (int i = 0; i < 4; i++) {
            float mn  = fmaxf(m[i], mt[i]);
            float scx = __expf(m[i] - mn);
            l[i] *= scx;
#pragma unroll
            for (int j = 0; j < 4; j++) o[i][j] *= scx;
            m[i] = mn;
            rs[i] = 0.f;
#pragma unroll
            for (int j = 0; j < 4; j++) {
                float p = __expf(s[i][j] - mn);
                Ps[(ty + 16*i)*65 + tx + 16*j] = p;
                rs[i] += p;
            }
        }
#pragma unroll
        for (int off = 8; off > 0; off >>= 1)
#pragma unroll
            for (int i = 0; i < 4; i++)
                rs[i] += __shfl_xor_sync(0xffffffffu, rs[i], off, 16);
#pragma unroll
        for (int i = 0; i < 4; i++) l[i] += rs[i];
        __syncthreads();

        // O += P @ V
#pragma unroll 8
        for (int kk = 0; kk < 64; kk++) {
            float p4[4], v4[4];
#pragma unroll
            for (int i = 0; i < 4; i++) p4[i] = Ps[(ty + 16*i)*65 + kk];
#pragma unroll
            for (int j = 0; j < 4; j++) v4[j] = Vs[kk*64 + tx + 16*j];
#pragma unroll
            for (int i = 0; i < 4; i++)
#pragma unroll
                for (int j = 0; j < 4; j++) o[i][j] += p4[i]*v4[j];
        }
        __syncthreads();
    }

    // epilogue: normalize; fully-masked rows -> 0 (matches nan_to_num)
    float* Hp = g_Hc + (size_t)b*SS*DD + h*DKK;
#pragma unroll
    for (int i = 0; i < 4; i++) {
        int q = qbase + ty + 16*i;
        bool zero = (q >= rowlen) || (collen <= 0) || (l[i] <= 0.f);
        float inv = zero ? 0.f : 1.0f / l[i];
#pragma unroll
        for (int j = 0; j < 4; j++)
            Hp[(size_t)q*DD + tx + 16*j] = o[i][j]*inv;
    }
}

// ---------------------------------------------------------------------------
extern "C" void kernel_launch(void* const* d_in, const int* in_sizes, int n_in,
                              void* d_out, int out_size) {
    const float* in_Q = (const float*)d_in[0];
    const float* in_K = (const float*)d_in[1];
    const float* in_V = (const float*)d_in[2];
    const int*   rm   = (const int*)d_in[3];
    const int*   cm   = (const int*)d_in[4];
    const float* WQ = (const float*)d_in[5];  const float* bQ = (const float*)d_in[6];
    const float* WK = (const float*)d_in[7];  const float* bK = (const float*)d_in[8];
    const float* WV = (const float*)d_in[9];  const float* bV = (const float*)d_in[10];
    const float* WO = (const float*)d_in[11]; const float* bO = (const float*)d_in[12];
    float* out = (float*)d_out;

    const int attn_smem = (65 + 65 + 64 + 65) * 64 * 4;   // 66304 B
    cudaFuncSetAttribute(attn_kernel, cudaFuncAttributeMaxDynamicSharedMemorySize, attn_smem);

    masklen_kernel<<<BB, 256>>>(rm, cm);

    dim3 g1(64, 8, 3);                 // M=4096 / 64, N=512 / 64, {Q,K,V}
    qkv_kernel<<<g1, 256>>>(in_Q, in_K, in_V, WQ, bQ, WK, bK, WV, bV);

    dim3 g2(1, 32, 16);                // q-tiles x (b*h)
    attn_kernel<<<g2, 256, attn_smem>>>();

    dim3 g3(64, 8, 1);
    oproj_kernel<<<g3, 256>>>(WO, bO, out);
}

// round 3
// speedup vs baseline: 3.9830x; 3.9830x over previous
#include <cuda_runtime.h>
#include <cstdint>

#define BB 2
#define SS 2048
#define DD 512
#define HH 8
#define DKK 64

// Scratch (static device globals: allocation-free per harness rules)
__device__ float g_Q[BB*SS*DD];
__device__ float g_K[BB*SS*DD];
__device__ float g_V[BB*SS*DD];
__device__ float g_Hc[BB*SS*DD];
__device__ int   g_len[2*BB];   // [rowlen[0..B), collen[0..B)]

// ---------------------------------------------------------------------------
// helpers (base-target PTX only: sm_80-era mma.sync + cp.async)
// ---------------------------------------------------------------------------
__device__ __forceinline__ uint32_t f2tf(float f) {
    uint32_t r; asm("cvt.rna.tf32.f32 %0, %1;" : "=r"(r) : "f"(f)); return r;
}
__device__ __forceinline__ float f2tff(float f) {
    uint32_t r; asm("cvt.rna.tf32.f32 %0, %1;" : "=r"(r) : "f"(f));
    return __uint_as_float(r);
}
__device__ __forceinline__ void mma_tf32(float* c, const uint32_t* a, const uint32_t* b) {
    asm volatile("mma.sync.aligned.m16n8k8.row.col.f32.tf32.tf32.f32 "
        "{%0,%1,%2,%3}, {%4,%5,%6,%7}, {%8,%9}, {%0,%1,%2,%3};"
        : "+f"(c[0]), "+f"(c[1]), "+f"(c[2]), "+f"(c[3])
        : "r"(a[0]), "r"(a[1]), "r"(a[2]), "r"(a[3]), "r"(b[0]), "r"(b[1]));
}
__device__ __forceinline__ uint32_t smem_u32(const void* p) {
    uint32_t a;
    asm("{ .reg .u64 t; cvta.to.shared.u64 t, %1; cvt.u32.u64 %0, t; }" : "=r"(a) : "l"(p));
    return a;
}
__device__ __forceinline__ void cpa16(uint32_t dst, const void* src) {
    asm volatile("cp.async.cg.shared.global [%0], [%1], 16;" :: "r"(dst), "l"(src));
}

// ---------------------------------------------------------------------------
// Mask length reduction
// ---------------------------------------------------------------------------
__global__ void masklen_kernel(const int* __restrict__ rm, const int* __restrict__ cm) {
    __shared__ int sr[256], sc[256];
    int b = blockIdx.x, t = threadIdx.x;
    int r = 0, c = 0;
    for (int s = t; s < SS; s += 256) { r += rm[b*SS + s]; c += cm[b*SS + s]; }
    sr[t] = r; sc[t] = c;
    __syncthreads();
    for (int o = 128; o > 0; o >>= 1) {
        if (t < o) { sr[t] += sr[t+o]; sc[t] += sc[t+o]; }
        __syncthreads();
    }
    if (t == 0) { g_len[b] = sr[0]; g_len[BB + b] = sc[0]; }
}

// ---------------------------------------------------------------------------
// mma.sync tf32 GEMM: C[4096|4096x512] = A[M,512] @ W[512,512]^T + bias
// CTA tile 128x128, K-chunk 32, cp.async double buffer. 256 threads (8 warps,
// warp tile 64x32 = 4x4 m16n8k8 tiles).
// smem floats: A0[0,4608) A1[4608,9216) B0[9216,13824) B1[13824,18432) bias[18432,18560)
// ---------------------------------------------------------------------------
#define GSTR 36
#define GEMM_SMEM (18560*4)

__device__ __forceinline__ void gemm_tc(const float* __restrict__ Ag,
                                        const float* __restrict__ Wg,
                                        const float* __restrict__ bg,
                                        float* __restrict__ Cg) {
    extern __shared__ float sg[];
    float* bias_s = sg + 18432;
    const uint32_t sb = smem_u32(sg);
    const int tid = threadIdx.x;
    const int wid = tid >> 5, lane = tid & 31, gid = lane >> 2, tig = lane & 3;
    const int warp_m = wid & 1, warp_n = wid >> 1;
    const int bm = blockIdx.x * 128, bn = blockIdx.y * 128;

    if (tid < 128) bias_s[tid] = bg[bn + tid];

    float acc[4][4][4];
#pragma unroll
    for (int a = 0; a < 4; a++)
#pragma unroll
        for (int b = 0; b < 4; b++)
#pragma unroll
            for (int k = 0; k < 4; k++) acc[a][b][k] = 0.f;

    const int r0 = tid >> 3, c0 = (tid & 7) << 2;
    const uint32_t dA = sb + (uint32_t)(r0*GSTR + c0) * 4;
    const uint32_t dB = sb + (uint32_t)(9216 + r0*GSTR + c0) * 4;
    const float* pA = Ag + (size_t)(bm + r0) * DD + c0;
    const float* pB = Wg + (size_t)(bn + r0) * DD + c0;
    const uint32_t STG = 4608 * 4;

#define LOAD_STAGE(cc, buf) do { \
    _Pragma("unroll") \
    for (int i = 0; i < 4; i++) { \
        cpa16(dA + (buf)*STG + (uint32_t)i*32*GSTR*4, pA + (size_t)i*32*DD + (cc)*32); \
        cpa16(dB + (buf)*STG + (uint32_t)i*32*GSTR*4, pB + (size_t)i*32*DD + (cc)*32); \
    } \
    asm volatile("cp.async.commit_group;"); \
} while (0)

    LOAD_STAGE(0, 0);

    for (int c = 0; c < 16; c++) {
        const int buf = c & 1;
        if (c + 1 < 16) {
            LOAD_STAGE(c + 1, buf ^ 1);
            asm volatile("cp.async.wait_group 1;");
        } else {
            asm volatile("cp.async.wait_group 0;");
        }
        __syncthreads();
        const float* As = sg + buf * 4608;
        const float* Bs = sg + 9216 + buf * 4608;
#pragma unroll
        for (int ks = 0; ks < 4; ks++) {
            const int k = ks * 8 + tig;
            uint32_t af[4][4], bf[4][2];
#pragma unroll
            for (int tm = 0; tm < 4; tm++) {
                int r = warp_m*64 + tm*16 + gid;
                af[tm][0] = f2tf(As[r*GSTR + k]);
                af[tm][1] = f2tf(As[(r+8)*GSTR + k]);
                af[tm][2] = f2tf(As[r*GSTR + k + 4]);
                af[tm][3] = f2tf(As[(r+8)*GSTR + k + 4]);
            }
#pragma unroll
            for (int tn = 0; tn < 4; tn++) {
                int n = warp_n*32 + tn*8 + gid;
                bf[tn][0] = f2tf(Bs[n*GSTR + k]);
                bf[tn][1] = f2tf(Bs[n*GSTR + k + 4]);
            }
#pragma unroll
            for (int tm = 0; tm < 4; tm++)
#pragma unroll
                for (int tn = 0; tn < 4; tn++)
                    mma_tf32(acc[tm][tn], af[tm], bf[tn]);
        }
        __syncthreads();
    }
#undef LOAD_STAGE

    // epilogue: add bias, write float2 pairs (c cols are contiguous)
#pragma unroll
    for (int tm = 0; tm < 4; tm++) {
        int r = bm + warp_m*64 + tm*16 + gid;
#pragma unroll
        for (int tn = 0; tn < 4; tn++) {
            int cc = warp_n*32 + tn*8 + tig*2;
            float b0 = bias_s[cc], b1 = bias_s[cc+1];
            float2 v0 = { acc[tm][tn][0] + b0, acc[tm][tn][1] + b1 };
            float2 v1 = { acc[tm][tn][2] + b0, acc[tm][tn][3] + b1 };
            *(float2*)(Cg + (size_t)r*DD + bn + cc) = v0;
            *(float2*)(Cg + (size_t)(r+8)*DD + bn + cc) = v1;
        }
    }
}

__global__ void __launch_bounds__(256, 1) qkv_tc_kernel(
        const float* __restrict__ inQ, const float* __restrict__ inK,
        const float* __restrict__ inV,
        const float* __restrict__ WQ, const float* __restrict__ bQ,
        const float* __restrict__ WK, const float* __restrict__ bK,
        const float* __restrict__ WV, const float* __restrict__ bV) {
    const float *A, *W, *bi; float* C;
    int z = blockIdx.z;
    if (z == 0)      { A = inQ; W = WQ; bi = bQ; C = g_Q; }
    else if (z == 1) { A = inK; W = WK; bi = bK; C = g_K; }
    else             { A = inV; W = WV; bi = bV; C = g_V; }
    gemm_tc(A, W, bi, C);
}

__global__ void __launch_bounds__(256, 1) oproj_tc_kernel(
        const float* __restrict__ WO, const float* __restrict__ bO,
        float* __restrict__ out) {
    gemm_tc(g_Hc, WO, bO, out);
}

// ---------------------------------------------------------------------------
// Flash attention with mma.sync tf32.
// 256 threads = 8 warps: warp_m = wid>>1 (16-row band), warp_n = wid&1.
// S: warp tile 16x32 (1 m-tile x 4 n-tiles, k=64). Online softmax on register
// fragments, cross-warp_n reduction via smem. P bounced via smem (aliases Ks)
// to re-fragment as A for PV. O: warp tile 16 rows x 32 d-cols (no combine).
// smem floats: Qs[0,4352) Ks/Ps[4352,8704) Vs/Obuf[8704,13056) red[13056,13312) linv[13312,13376)
// ---------------------------------------------------------------------------
#define ASTR 68
#define ATTN_SMEM (13376*4)

__global__ void __launch_bounds__(256, 1) attn_kernel() {
    extern __shared__ float sa[];
    float* Qs = sa;
    float* Ks = sa + 4352;          // aliased by Ps
    float* Vs = sa + 8704;          // aliased by Obuf
    float* red = sa + 13056;        // [64][4]: cols 0,1 max; 2,3 sum
    float* linv = sa + 13312;       // [64]

    const int bh = blockIdx.z;
    const int b = bh >> 3, h = bh & 7;
    const int qt = (int)gridDim.y - 1 - (int)blockIdx.y;   // heavy tiles first
    const int qbase = qt << 6;
    const int rowlen = g_len[b], collen = g_len[BB + b];
    const int tid = threadIdx.x, wid = tid >> 5, lane = tid & 31;
    const int gid = lane >> 2, tig = lane & 3;
    const int warp_m = wid >> 1, warp_n = wid & 1;
    float* Hp = g_Hc + (size_t)b*SS*DD + h*DKK;

    if (qbase >= rowlen || collen <= 0) {
#pragma unroll
        for (int p = 0; p < 4; p++) {
            int r = p*16 + (tid >> 4), c = (tid & 15) << 2;
            float4 z = {0.f, 0.f, 0.f, 0.f};
            *(float4*)(Hp + (size_t)(qbase + r)*DD + c) = z;
        }
        return;
    }

    const float* Qp = g_Q + (size_t)b*SS*DD + h*DKK;
    const float* Kp = g_K + (size_t)b*SS*DD + h*DKK;
    const float* Vp = g_V + (size_t)b*SS*DD + h*DKK;

    // Q tile, tf32-rounded at store (frag loads then skip cvt)
#pragma unroll
    for (int i = 0; i < 4; i++) {
        int e = tid + i*256, r = e >> 4, c = (e & 15) << 2;
        float4 v = *(const float4*)(Qp + (size_t)(qbase + r)*DD + c);
        Qs[r*ASTR + c]   = f2tff(v.x); Qs[r*ASTR + c+1] = f2tff(v.y);
        Qs[r*ASTR + c+2] = f2tff(v.z); Qs[r*ASTR + c+3] = f2tff(v.w);
    }

    float m0 = -1e30f, m1 = -1e30f, l0 = 0.f, l1 = 0.f;
    float oacc[4][4];
#pragma unroll
    for (int tn = 0; tn < 4; tn++)
#pragma unroll
        for (int i = 0; i < 4; i++) oacc[tn][i] = 0.f;

    const int rr0 = warp_m*16 + gid, rr1 = rr0 + 8;
    const int q0 = qbase + rr0, q1 = qbase + rr1;

    const int kmax = min(qbase + 64, collen);
    const int nk = (kmax + 63) >> 6;

    for (int kt = 0; kt < nk; kt++) {
        const int kbase = kt << 6;
        __syncthreads();   // prev iter's Ps(=Ks)/Vs readers done before overwrite
#pragma unroll
        for (int i = 0; i < 4; i++) {
            int e = tid + i*256, r = e >> 4, c = (e & 15) << 2;
            float4 vk = *(const float4*)(Kp + (size_t)(kbase + r)*DD + c);
            Ks[r*ASTR + c]   = f2tff(vk.x); Ks[r*ASTR + c+1] = f2tff(vk.y);
            Ks[r*ASTR + c+2] = f2tff(vk.z); Ks[r*ASTR + c+3] = f2tff(vk.w);
            float4 vv = *(const float4*)(Vp + (size_t)(kbase + r)*DD + c);
            Vs[r*ASTR + c]   = f2tff(vv.x); Vs[r*ASTR + c+1] = f2tff(vv.y);
            Vs[r*ASTR + c+2] = f2tff(vv.z); Vs[r*ASTR + c+3] = f2tff(vv.w);
        }
        __syncthreads();

        // S = Q K^T  (warp: rows rr0 band, cols warp_n*32..+32)
        float sacc[4][4];
#pragma unroll
        for (int tn = 0; tn < 4; tn++)
#pragma unroll
            for (int i = 0; i < 4; i++) sacc[tn][i] = 0.f;
#pragma unroll
        for (int ks = 0; ks < 8; ks++) {
            const int k = ks*8 + tig;
            uint32_t af[4];
            af[0] = __float_as_uint(Qs[rr0*ASTR + k]);
            af[1] = __float_as_uint(Qs[rr1*ASTR + k]);
            af[2] = __float_as_uint(Qs[rr0*ASTR + k + 4]);
            af[3] = __float_as_uint(Qs[rr1*ASTR + k + 4]);
#pragma unroll
            for (int tn = 0; tn < 4; tn++) {
                const int n = warp_n*32 + tn*8 + gid;
                uint32_t bf[2] = { __float_as_uint(Ks[n*ASTR + k]),
                                   __float_as_uint(Ks[n*ASTR + k + 4]) };
                mma_tf32(sacc[tn], af, bf);
            }
        }

        // scale + causal/padding mask
#pragma unroll
        for (int tn = 0; tn < 4; tn++) {
            const int kc = kbase + warp_n*32 + tn*8 + tig*2;
            sacc[tn][0] = (kc   <= q0 && q0 < rowlen && kc   < collen) ? sacc[tn][0]*0.125f : -1e30f;
            sacc[tn][1] = (kc+1 <= q0 && q0 < rowlen && kc+1 < collen) ? sacc[tn][1]*0.125f : -1e30f;
            sacc[tn][2] = (kc   <= q1 && q1 < rowlen && kc   < collen) ? sacc[tn][2]*0.125f : -1e30f;
            sacc[tn][3] = (kc+1 <= q1 && q1 < rowlen && kc+1 < collen) ? sacc[tn][3]*0.125f : -1e30f;
        }

        // row max: local (8 cols) -> quad shfl -> cross-warp_n via smem
        float a0 = -1e30f, a1 = -1e30f;
#pragma unroll
        for (int tn = 0; tn < 4; tn++) {
            a0 = fmaxf(a0, fmaxf(sacc[tn][0], sacc[tn][1]));
            a1 = fmaxf(a1, fmaxf(sacc[tn][2], sacc[tn][3]));
        }
        a0 = fmaxf(a0, __shfl_xor_sync(0xffffffffu, a0, 1));
        a0 = fmaxf(a0, __shfl_xor_sync(0xffffffffu, a0, 2));
        a1 = fmaxf(a1, __shfl_xor_sync(0xffffffffu, a1, 1));
        a1 = fmaxf(a1, __shfl_xor_sync(0xffffffffu, a1, 2));
        if (tig == 0) { red[rr0*4 + warp_n] = a0; red[rr1*4 + warp_n] = a1; }
        __syncthreads();

        const float mn0 = fmaxf(m0, fmaxf(red[rr0*4], red[rr0*4 + 1]));
        const float mn1 = fmaxf(m1, fmaxf(red[rr1*4], red[rr1*4 + 1]));
        const float sc0 = __expf(m0 - mn0), sc1 = __expf(m1 - mn1);
        l0 *= sc0; l1 *= sc1; m0 = mn0; m1 = mn1;
#pragma unroll
        for (int tn = 0; tn < 4; tn++) {
            oacc[tn][0] *= sc0; oacc[tn][1] *= sc0;
            oacc[tn][2] *= sc1; oacc[tn][3] *= sc1;
        }

        // exp, P to smem (tf32-rounded), row sums
        float* Ps = Ks;
        float rs0 = 0.f, rs1 = 0.f;
#pragma unroll
        for (int tn = 0; tn < 4; tn++) {
            float p0 = __expf(sacc[tn][0] - mn0), p1 = __expf(sacc[tn][1] - mn0);
            float p2 = __expf(sacc[tn][2] - mn1), p3 = __expf(sacc[tn][3] - mn1);
            rs0 += p0 + p1; rs1 += p2 + p3;
            const int cc = warp_n*32 + tn*8 + tig*2;
            *(float2*)(Ps + rr0*ASTR + cc) = make_float2(f2tff(p0), f2tff(p1));
            *(float2*)(Ps + rr1*ASTR + cc) = make_float2(f2tff(p2), f2tff(p3));
        }
        rs0 += __shfl_xor_sync(0xffffffffu, rs0, 1);
        rs0 += __shfl_xor_sync(0xffffffffu, rs0, 2);
        rs1 += __shfl_xor_sync(0xffffffffu, rs1, 1);
        rs1 += __shfl_xor_sync(0xffffffffu, rs1, 2);
        if (tig == 0) { red[rr0*4 + 2 + warp_n] = rs0; red[rr1*4 + 2 + warp_n] = rs1; }
        __syncthreads();
        l0 += red[rr0*4 + 2] + red[rr0*4 + 3];
        l1 += red[rr1*4 + 2] + red[rr1*4 + 3];

        // O += P V   (warp: rows rr0 band, d-cols warp_n*32..+32, k full 64)
#pragma unroll
        for (int ks = 0; ks < 8; ks++) {
            const int k = ks*8 + tig;
            uint32_t af[4];
            af[0] = __float_as_uint(Ps[rr0*ASTR + k]);
            af[1] = __float_as_uint(Ps[rr1*ASTR + k]);
            af[2] = __float_as_uint(Ps[rr0*ASTR + k + 4]);
            af[3] = __float_as_uint(Ps[rr1*ASTR + k + 4]);
#pragma unroll
            for (int tn = 0; tn < 4; tn++) {
                const int d = warp_n*32 + tn*8 + gid;
                uint32_t bf[2] = { __float_as_uint(Vs[k*ASTR + d]),
                                   __float_as_uint(Vs[(k+4)*ASTR + d]) };
                mma_tf32(oacc[tn], af, bf);
            }
        }
    }

    __syncthreads();   // all PV reads of Vs done before Obuf overwrite
    float* Ob = Vs;
#pragma unroll
    for (int tn = 0; tn < 4; tn++) {
        const int cc = warp_n*32 + tn*8 + tig*2;
        *(float2*)(Ob + rr0*ASTR + cc) = make_float2(oacc[tn][0], oacc[tn][1]);
        *(float2*)(Ob + rr1*ASTR + cc) = make_float2(oacc[tn][2], oacc[tn][3]);
    }
    if (warp_n == 0 && tig == 0) {
        linv[rr0] = (q0 < rowlen && l0 > 0.f) ? 1.f / l0 : 0.f;
        linv[rr1] = (q1 < rowlen && l1 > 0.f) ? 1.f / l1 : 0.f;
    }
    __syncthreads();
#pragma unroll
    for (int p = 0; p < 4; p++) {
        int r = p*16 + (tid >> 4), c = (tid & 15) << 2;
        float iv = linv[r];
        float4 v = { Ob[r*ASTR + c]*iv, Ob[r*ASTR + c+1]*iv,
                     Ob[r*ASTR + c+2]*iv, Ob[r*ASTR + c+3]*iv };
        *(float4*)(Hp + (size_t)(qbase + r)*DD + c) = v;
    }
}

// ---------------------------------------------------------------------------
extern "C" void kernel_launch(void* const* d_in, const int* in_sizes, int n_in,
                              void* d_out, int out_size) {
    const float* in_Q = (const float*)d_in[0];
    const float* in_K = (const float*)d_in[1];
    const float* in_V = (const float*)d_in[2];
    const int*   rm   = (const int*)d_in[3];
    const int*   cm   = (const int*)d_in[4];
    const float* WQ = (const float*)d_in[5];  const float* bQ = (const float*)d_in[6];
    const float* WK = (const float*)d_in[7];  const float* bK = (const float*)d_in[8];
    const float* WV = (const float*)d_in[9];  const float* bV = (const float*)d_in[10];
    const float* WO = (const float*)d_in[11]; const float* bO = (const float*)d_in[12];
    float* out = (float*)d_out;

    cudaFuncSetAttribute(qkv_tc_kernel,   cudaFuncAttributeMaxDynamicSharedMemorySize, GEMM_SMEM);
    cudaFuncSetAttribute(oproj_tc_kernel, cudaFuncAttributeMaxDynamicSharedMemorySize, GEMM_SMEM);
    cudaFuncSetAttribute(attn_kernel,     cudaFuncAttributeMaxDynamicSharedMemorySize, ATTN_SMEM);

    masklen_kernel<<<BB, 256>>>(rm, cm);

    dim3 g1(32, 4, 3);                 // 128x128 tiles: M=4096/128, N=512/128, {Q,K,V}
    qkv_tc_kernel<<<g1, 256, GEMM_SMEM>>>(in_Q, in_K, in_V, WQ, bQ, WK, bK, WV, bV);

    dim3 g2(1, 32, 16);                // q-tiles x (b*h)
    attn_kernel<<<g2, 256, ATTN_SMEM>>>();

    dim3 g3(32, 4, 1);
    oproj_tc_kernel<<<g3, 256, GEMM_SMEM>>>(WO, bO, out);
}

// round 5
// speedup vs baseline: 4.1940x; 1.0530x over previous
#include <cuda_runtime.h>
#include <cstdint>

#define BB 2
#define SS 2048
#define DD 512
#define HH 8
#define DKK 64

// Scratch (static device globals: allocation-free per harness rules)
__device__ float g_QKV[3*BB*SS*DD];     // tf32-rounded Q,K,V projections
__device__ float g_Hc[BB*SS*DD];        // tf32-rounded attention output
__device__ float g_Wqkv[3*DD*DD];       // tf32-rounded concat [WQ;WK;WV] rows
__device__ float g_Wo[DD*DD];           // tf32-rounded WO
__device__ float g_bqkv[3*DD];          // concat biases
__device__ int   g_len[2*BB];           // [rowlen[0..B), collen[0..B)]

// ---------------------------------------------------------------------------
// helpers (base-target PTX only: sm_80-era mma.sync + cp.async)
// ---------------------------------------------------------------------------
__device__ __forceinline__ uint32_t f2tf(float f) {
    uint32_t r; asm("cvt.rna.tf32.f32 %0, %1;" : "=r"(r) : "f"(f)); return r;
}
__device__ __forceinline__ float f2tff(float f) {
    uint32_t r; asm("cvt.rna.tf32.f32 %0, %1;" : "=r"(r) : "f"(f));
    return __uint_as_float(r);
}
__device__ __forceinline__ void mma_tf32(float* c, const uint32_t* a, const uint32_t* b) {
    asm volatile("mma.sync.aligned.m16n8k8.row.col.f32.tf32.tf32.f32 "
        "{%0,%1,%2,%3}, {%4,%5,%6,%7}, {%8,%9}, {%0,%1,%2,%3};"
        : "+f"(c[0]), "+f"(c[1]), "+f"(c[2]), "+f"(c[3])
        : "r"(a[0]), "r"(a[1]), "r"(a[2]), "r"(a[3]), "r"(b[0]), "r"(b[1]));
}
__device__ __forceinline__ uint32_t smem_u32(const void* p) {
    uint32_t a;
    asm("{ .reg .u64 t; cvta.to.shared.u64 t, %1; cvt.u32.u64 %0, t; }" : "=r"(a) : "l"(p));
    return a;
}
__device__ __forceinline__ void cpa16(uint32_t dst, const void* src) {
    asm volatile("cp.async.cg.shared.global [%0], [%1], 16;" :: "r"(dst), "l"(src));
}
__device__ __forceinline__ void cpa_commit() {
    asm volatile("cp.async.commit_group;");
}

// ---------------------------------------------------------------------------
// Prep kernel: mask lengths + tf32 weight conversion + bias concat
// blocks 0,1: masklen(b); blocks 2..65: convert 4x512x512 weights
// ---------------------------------------------------------------------------
__global__ void prep_kernel(const int* __restrict__ rm, const int* __restrict__ cm,
                            const float* __restrict__ WQ, const float* __restrict__ WK,
                            const float* __restrict__ WV, const float* __restrict__ WO,
                            const float* __restrict__ bQ, const float* __restrict__ bK,
                            const float* __restrict__ bV) {
    int blk = blockIdx.x, t = threadIdx.x;
    if (blk < 2) {
        __shared__ int sr[256], sc[256];
        int b = blk;
        int r = 0, c = 0;
        for (int s = t; s < SS; s += 256) { r += rm[b*SS + s]; c += cm[b*SS + s]; }
        sr[t] = r; sc[t] = c;
        __syncthreads();
        for (int o = 128; o > 0; o >>= 1) {
            if (t < o) { sr[t] += sr[t+o]; sc[t] += sc[t+o]; }
            __syncthreads();
        }
        if (t == 0) { g_len[b] = sr[0]; g_len[BB + b] = sc[0]; }
        if (blk == 0)
            for (int i = t; i < DD; i += 256) {
                g_bqkv[i] = bQ[i]; g_bqkv[DD + i] = bK[i]; g_bqkv[2*DD + i] = bV[i];
            }
        return;
    }
    // weight conversion: 4 matrices of 65536 float4 each; 64 blocks x 256 thr x 16 f4
    int base = (blk - 2) * 4096 + t;      // float4 index within the 262144 total
    const float* srcs[4] = { WQ, WK, WV, WO };
#pragma unroll
    for (int i = 0; i < 16; i++) {
        int f4 = base + i * 256;
        int mat = f4 >> 16;               // 65536 float4 per matrix
        int off = (f4 & 65535) << 2;
        float4 v = *(const float4*)(srcs[mat] + off);
        float4 o = { f2tff(v.x), f2tff(v.y), f2tff(v.z), f2tff(v.w) };
        if (mat < 3) *(float4*)(g_Wqkv + mat*DD*DD + off) = o;
        else         *(float4*)(g_Wo + off) = o;
    }
}

// ---------------------------------------------------------------------------
// mma.sync tf32 GEMM, 3-stage cp.async, one sync per K-chunk.
// BM x 128 tile, K chunks of 32. 256 threads, 8 warps; warp tile (BM/2) x 32.
// B (weights) pre-converted to tf32; A converted iff CVT_A.
// smem floats: stage s at s*(BM*36+4608): A[BM][36], B[128][36]; bias after.
// ---------------------------------------------------------------------------
template<int BM, bool CVT_A, bool ROUND_OUT>
__device__ __forceinline__ void gemm_tc(const float* __restrict__ Ag,
                                        const float* __restrict__ Wg,
                                        const float* __restrict__ bg,
                                        float* __restrict__ Cg,
                                        int bm, int bn_local) {
    extern __shared__ float sg[];
    constexpr int SS_A  = BM * 36;
    constexpr int SS_AB = SS_A + 4608;
    constexpr int TM = BM / 32;
    float* bias_s = sg + 3 * SS_AB;
    const uint32_t sb = smem_u32(sg);
    const int tid = threadIdx.x;
    const int wid = tid >> 5, lane = tid & 31, gid = lane >> 2, tig = lane & 3;
    const int warp_m = wid & 1, warp_n = wid >> 1;

    if (tid < 128) bias_s[tid] = bg[tid];

    float acc[TM][4][4];
#pragma unroll
    for (int a = 0; a < TM; a++)
#pragma unroll
        for (int b = 0; b < 4; b++)
#pragma unroll
            for (int k = 0; k < 4; k++) acc[a][b][k] = 0.f;

    const int r0 = tid >> 3, c0 = (tid & 7) << 2;
    const float* pA = Ag + (size_t)(bm + r0) * DD + c0;
    const float* pB = Wg + (size_t)(bn_local + r0) * DD + c0;   // FIX: include N-tile offset

#define G_LOAD(cc, buf) do { \
    uint32_t dA = sb + (uint32_t)((buf)*SS_AB + r0*36 + c0) * 4; \
    uint32_t dB = sb + (uint32_t)((buf)*SS_AB + SS_A + r0*36 + c0) * 4; \
    _Pragma("unroll") \
    for (int i = 0; i < BM/32; i++) \
        cpa16(dA + (uint32_t)i*32*36*4, pA + (size_t)i*32*DD + (cc)*32); \
    _Pragma("unroll") \
    for (int i = 0; i < 4; i++) \
        cpa16(dB + (uint32_t)i*32*36*4, pB + (size_t)i*32*DD + (cc)*32); \
} while (0)

    G_LOAD(0, 0); cpa_commit();
    G_LOAD(1, 1); cpa_commit();

    for (int c = 0; c < 16; c++) {
        asm volatile("cp.async.wait_group 1;");
        __syncthreads();
        if (c + 2 < 16) { int buf = (c + 2) % 3; G_LOAD(c + 2, buf); }
        cpa_commit();

        const float* As = sg + (c % 3) * SS_AB;
        const float* Bs = As + SS_A;
#pragma unroll
        for (int ks = 0; ks < 4; ks++) {
            const int k = ks * 8 + tig;
            uint32_t af[TM][4], bf[4][2];
#pragma unroll
            for (int tm = 0; tm < TM; tm++) {
                int r = warp_m*(BM/2) + tm*16 + gid;
                if (CVT_A) {
                    af[tm][0] = f2tf(As[r*36 + k]);
                    af[tm][1] = f2tf(As[(r+8)*36 + k]);
                    af[tm][2] = f2tf(As[r*36 + k + 4]);
                    af[tm][3] = f2tf(As[(r+8)*36 + k + 4]);
                } else {
                    af[tm][0] = __float_as_uint(As[r*36 + k]);
                    af[tm][1] = __float_as_uint(As[(r+8)*36 + k]);
                    af[tm][2] = __float_as_uint(As[r*36 + k + 4]);
                    af[tm][3] = __float_as_uint(As[(r+8)*36 + k + 4]);
                }
            }
#pragma unroll
            for (int tn = 0; tn < 4; tn++) {
                int n = warp_n*32 + tn*8 + gid;
                bf[tn][0] = __float_as_uint(Bs[n*36 + k]);
                bf[tn][1] = __float_as_uint(Bs[n*36 + k + 4]);
            }
#pragma unroll
            for (int tm = 0; tm < TM; tm++)
#pragma unroll
                for (int tn = 0; tn < 4; tn++)
                    mma_tf32(acc[tm][tn], af[tm], bf[tn]);
        }
    }
#undef G_LOAD

#pragma unroll
    for (int tm = 0; tm < TM; tm++) {
        int r = bm + warp_m*(BM/2) + tm*16 + gid;
#pragma unroll
        for (int tn = 0; tn < 4; tn++) {
            int cc = warp_n*32 + tn*8 + tig*2;
            float b0 = bias_s[cc], b1 = bias_s[cc+1];
            float2 v0, v1;
            if (ROUND_OUT) {
                v0 = make_float2(f2tff(acc[tm][tn][0] + b0), f2tff(acc[tm][tn][1] + b1));
                v1 = make_float2(f2tff(acc[tm][tn][2] + b0), f2tff(acc[tm][tn][3] + b1));
            } else {
                v0 = make_float2(acc[tm][tn][0] + b0, acc[tm][tn][1] + b1);
                v1 = make_float2(acc[tm][tn][2] + b0, acc[tm][tn][3] + b1);
            }
            *(float2*)(Cg + (size_t)r*DD + bn_local + cc) = v0;
            *(float2*)(Cg + (size_t)(r+8)*DD + bn_local + cc) = v1;
        }
    }
}

#define GEMM_SMEM_128 ((3*(128*36+4608) + 128)*4)
#define GEMM_SMEM_64  ((3*(64*36+4608)  + 128)*4)

// QKV: one GEMM, M=4096, N=1536 (concat). grid (32, 12).
__global__ void __launch_bounds__(256, 2) qkv_tc_kernel(const float* __restrict__ inQ,
                                                        const float* __restrict__ inK,
                                                        const float* __restrict__ inV) {
    int bn = blockIdx.y * 128;
    int z = bn >> 9;                          // which of Q/K/V
    const float* A = (z == 0) ? inQ : (z == 1) ? inK : inV;
    gemm_tc<128, true, true>(A, g_Wqkv + (size_t)z*DD*DD, g_bqkv + bn,
                             g_QKV + (size_t)z*BB*SS*DD,
                             blockIdx.x * 128, bn & 511);
}

// O projection: M=4096, N=512, 64x128 tiles. grid (64, 4).
__global__ void __launch_bounds__(256, 2) oproj_tc_kernel(const float* __restrict__ bO,
                                                          float* __restrict__ out) {
    gemm_tc<64, false, false>(g_Hc, g_Wo, bO + blockIdx.y * 128, out,
                              blockIdx.x * 64, blockIdx.y * 128);
}

// ---------------------------------------------------------------------------
// Flash attention v2: Br=128 per CTA, 8 warps, warp owns 16 full rows.
// Warp-local softmax (quad shfls only). P via warp-private smem + syncwarp.
// K/V double-buffered cp.async: ONE __syncthreads per k-tile.
// smem floats: Q[128][68]@0  K[2][64][68]@8704  V[2][64][72]@17408  P[8][16][68]@26624
// ---------------------------------------------------------------------------
#define A_Q   0
#define A_K0  8704
#define A_V0  17408
#define A_P   26624
#define ATTN_SMEM (35328*4)

__global__ void __launch_bounds__(256, 1) attn_kernel() {
    extern __shared__ float sa[];
    const uint32_t sb = smem_u32(sa);

    const int bh = blockIdx.z;
    const int b = bh >> 3, h = bh & 7;
    const int qt = 15 - (int)blockIdx.y;      // heavy tiles first
    const int qbase = qt << 7;                // 128 rows per CTA
    const int rowlen = g_len[b], collen = g_len[BB + b];
    const int tid = threadIdx.x, wid = tid >> 5, lane = tid & 31;
    const int gid = lane >> 2, tig = lane & 3;
    float* Hp = g_Hc + (size_t)b*SS*DD + h*DKK;

    if (qbase >= rowlen || collen <= 0) {
#pragma unroll
        for (int i = 0; i < 8; i++) {
            int e = tid + i*256, r = e >> 4, c = (e & 15) << 2;
            float4 z = {0.f, 0.f, 0.f, 0.f};
            *(float4*)(Hp + (size_t)(qbase + r)*DD + c) = z;
        }
        return;
    }

    const float* Qp = g_QKV + 0*(size_t)BB*SS*DD + (size_t)b*SS*DD + h*DKK;
    const float* Kp = g_QKV + 1*(size_t)BB*SS*DD + (size_t)b*SS*DD + h*DKK;
    const float* Vp = g_QKV + 2*(size_t)BB*SS*DD + (size_t)b*SS*DD + h*DKK;

    const int kmax = min(qbase + 128, collen);
    const int nk = (kmax + 63) >> 6;

    // prologue: Q tile (128x64) + K/V tile 0, one commit group
#pragma unroll
    for (int i = 0; i < 8; i++) {
        int e = tid + i*256, r = e >> 4, c = (e & 15) << 2;
        cpa16(sb + (uint32_t)(A_Q + r*68 + c)*4, Qp + (size_t)(qbase + r)*DD + c);
    }
#define KV_LOAD(kb, s) do { \
    _Pragma("unroll") \
    for (int i = 0; i < 4; i++) { \
        int e = tid + i*256, r = e >> 4, c = (e & 15) << 2; \
        cpa16(sb + (uint32_t)(A_K0 + (s)*4352 + r*68 + c)*4, Kp + (size_t)((kb) + r)*DD + c); \
        cpa16(sb + (uint32_t)(A_V0 + (s)*4608 + r*72 + c)*4, Vp + (size_t)((kb) + r)*DD + c); \
    } \
} while (0)
    KV_LOAD(0, 0); cpa_commit();

    const int wr = wid * 16;
    const int q0 = qbase + wr + gid, q1 = q0 + 8;
    float m0 = -1e30f, m1 = -1e30f, l0 = 0.f, l1 = 0.f;
    float oacc[8][4];
#pragma unroll
    for (int nt = 0; nt < 8; nt++)
#pragma unroll
        for (int i = 0; i < 4; i++) oacc[nt][i] = 0.f;

    float* Pw = sa + A_P + wid * 1088;        // warp-private 16x68

    for (int kt = 0; kt < nk; kt++) {
        const int kbase = kt << 6;
        const int buf = kt & 1;
        asm volatile("cp.async.wait_group 0;");
        __syncthreads();
        if (kt + 1 < nk) KV_LOAD(kbase + 64, buf ^ 1);
        cpa_commit();

        const float* Ks = sa + A_K0 + buf*4352;
        const float* Vs = sa + A_V0 + buf*4608;
        const float* Qs = sa + A_Q;

        // S = Q K^T : warp tile 16 x 64
        float sacc[8][4];
#pragma unroll
        for (int nt = 0; nt < 8; nt++)
#pragma unroll
            for (int i = 0; i < 4; i++) sacc[nt][i] = 0.f;
#pragma unroll
        for (int ks = 0; ks < 8; ks++) {
            const int k = ks*8 + tig;
            uint32_t af[4];
            af[0] = __float_as_uint(Qs[(wr+gid)*68 + k]);
            af[1] = __float_as_uint(Qs[(wr+gid+8)*68 + k]);
            af[2] = __float_as_uint(Qs[(wr+gid)*68 + k + 4]);
            af[3] = __float_as_uint(Qs[(wr+gid+8)*68 + k + 4]);
#pragma unroll
            for (int nt = 0; nt < 8; nt++) {
                const int n = nt*8 + gid;
                uint32_t bf[2] = { __float_as_uint(Ks[n*68 + k]),
                                   __float_as_uint(Ks[n*68 + k + 4]) };
                mma_tf32(sacc[nt], af, bf);
            }
        }

        // scale + causal/padding mask
#pragma unroll
        for (int nt = 0; nt < 8; nt++) {
            const int kc = kbase + nt*8 + tig*2;
            sacc[nt][0] = (kc   <= q0 && q0 < rowlen && kc   < collen) ? sacc[nt][0]*0.125f : -1e30f;
            sacc[nt][1] = (kc+1 <= q0 && q0 < rowlen && kc+1 < collen) ? sacc[nt][1]*0.125f : -1e30f;
            sacc[nt][2] = (kc   <= q1 && q1 < rowlen && kc   < collen) ? sacc[nt][2]*0.125f : -1e30f;
            sacc[nt][3] = (kc+1 <= q1 && q1 < rowlen && kc+1 < collen) ? sacc[nt][3]*0.125f : -1e30f;
        }

        // warp-local row max (quad shfls)
        float a0 = -1e30f, a1 = -1e30f;
#pragma unroll
        for (int nt = 0; nt < 8; nt++) {
            a0 = fmaxf(a0, fmaxf(sacc[nt][0], sacc[nt][1]));
            a1 = fmaxf(a1, fmaxf(sacc[nt][2], sacc[nt][3]));
        }
        a0 = fmaxf(a0, __shfl_xor_sync(0xffffffffu, a0, 1));
        a0 = fmaxf(a0, __shfl_xor_sync(0xffffffffu, a0, 2));
        a1 = fmaxf(a1, __shfl_xor_sync(0xffffffffu, a1, 1));
        a1 = fmaxf(a1, __shfl_xor_sync(0xffffffffu, a1, 2));

        const float mn0 = fmaxf(m0, a0), mn1 = fmaxf(m1, a1);
        const float sc0 = __expf(m0 - mn0), sc1 = __expf(m1 - mn1);
        l0 *= sc0; l1 *= sc1; m0 = mn0; m1 = mn1;
#pragma unroll
        for (int nt = 0; nt < 8; nt++) {
            oacc[nt][0] *= sc0; oacc[nt][1] *= sc0;
            oacc[nt][2] *= sc1; oacc[nt][3] *= sc1;
        }

        // exp, P to warp-private smem (tf32-rounded), row sums
        float rs0 = 0.f, rs1 = 0.f;
#pragma unroll
        for (int nt = 0; nt < 8; nt++) {
            float p0 = __expf(sacc[nt][0] - mn0), p1 = __expf(sacc[nt][1] - mn0);
            float p2 = __expf(sacc[nt][2] - mn1), p3 = __expf(sacc[nt][3] - mn1);
            rs0 += p0 + p1; rs1 += p2 + p3;
            const int cc = nt*8 + tig*2;
            *(float2*)(Pw + gid*68 + cc)     = make_float2(f2tff(p0), f2tff(p1));
            *(float2*)(Pw + (gid+8)*68 + cc) = make_float2(f2tff(p2), f2tff(p3));
        }
        rs0 += __shfl_xor_sync(0xffffffffu, rs0, 1);
        rs0 += __shfl_xor_sync(0xffffffffu, rs0, 2);
        rs1 += __shfl_xor_sync(0xffffffffu, rs1, 1);
        rs1 += __shfl_xor_sync(0xffffffffu, rs1, 2);
        l0 += rs0; l1 += rs1;
        __syncwarp();

        // O += P V   (warp tile 16 rows x 64 d-cols, k = 64)
#pragma unroll
        for (int ks = 0; ks < 8; ks++) {
            const int k = ks*8 + tig;
            uint32_t af[4];
            af[0] = __float_as_uint(Pw[gid*68 + k]);
            af[1] = __float_as_uint(Pw[(gid+8)*68 + k]);
            af[2] = __float_as_uint(Pw[gid*68 + k + 4]);
            af[3] = __float_as_uint(Pw[(gid+8)*68 + k + 4]);
#pragma unroll
            for (int nt = 0; nt < 8; nt++) {
                const int d = nt*8 + gid;
                uint32_t bf[2] = { __float_as_uint(Vs[k*72 + d]),
                                   __float_as_uint(Vs[(k+4)*72 + d]) };
                mma_tf32(oacc[nt], af, bf);
            }
        }
        __syncwarp();   // Pw reads done before next tile's writes
    }
#undef KV_LOAD

    // epilogue: normalize, round for oproj's tf32 input, write direct to gmem
    const float inv0 = (q0 < rowlen && l0 > 0.f) ? 1.f / l0 : 0.f;
    const float inv1 = (q1 < rowlen && l1 > 0.f) ? 1.f / l1 : 0.f;
#pragma unroll
    for (int nt = 0; nt < 8; nt++) {
        const int cc = nt*8 + tig*2;
        *(float2*)(Hp + (size_t)q0*DD + cc) =
            make_float2(f2tff(oacc[nt][0]*inv0), f2tff(oacc[nt][1]*inv0));
        *(float2*)(Hp + (size_t)q1*DD + cc) =
            make_float2(f2tff(oacc[nt][2]*inv1), f2tff(oacc[nt][3]*inv1));
    }
}

// ---------------------------------------------------------------------------
extern "C" void kernel_launch(void* const* d_in, const int* in_sizes, int n_in,
                              void* d_out, int out_size) {
    const float* in_Q = (const float*)d_in[0];
    const float* in_K = (const float*)d_in[1];
    const float* in_V = (const float*)d_in[2];
    const int*   rm   = (const int*)d_in[3];
    const int*   cm   = (const int*)d_in[4];
    const float* WQ = (const float*)d_in[5];  const float* bQ = (const float*)d_in[6];
    const float* WK = (const float*)d_in[7];  const float* bK = (const float*)d_in[8];
    const float* WV = (const float*)d_in[9];  const float* bV = (const float*)d_in[10];
    const float* WO = (const float*)d_in[11]; const float* bO = (const float*)d_in[12];
    float* out = (float*)d_out;

    cudaFuncSetAttribute(qkv_tc_kernel,   cudaFuncAttributeMaxDynamicSharedMemorySize, GEMM_SMEM_128);
    cudaFuncSetAttribute(oproj_tc_kernel, cudaFuncAttributeMaxDynamicSharedMemorySize, GEMM_SMEM_64);
    cudaFuncSetAttribute(attn_kernel,     cudaFuncAttributeMaxDynamicSharedMemorySize, ATTN_SMEM);

    prep_kernel<<<66, 256>>>(rm, cm, WQ, WK, WV, WO, bQ, bK, bV);

    dim3 g1(32, 12);                   // M=4096/128, N=1536/128
    qkv_tc_kernel<<<g1, 256, GEMM_SMEM_128>>>(in_Q, in_K, in_V);

    dim3 g2(1, 16, 16);                // 128-row q-tiles x (b*h)
    attn_kernel<<<g2, 256, ATTN_SMEM>>>();

    dim3 g3(64, 4);                    // M=4096/64, N=512/128
    oproj_tc_kernel<<<g3, 256, GEMM_SMEM_64>>>(bO, out);
}

// round 7
// speedup vs baseline: 4.9558x; 1.1816x over previous
#include <cuda_runtime.h>
#include <cuda_fp16.h>
#include <cstdint>

#define BB 2
#define SS 2048
#define DD 512
#define HH 8
#define DKK 64

// Scratch (static device globals: allocation-free per harness rules)
__device__ __half g_h16[3*BB*HH*SS*DKK];   // fp16 per-head Q,K,V: [z][b][h][s][64]
__device__ float  g_Hc[BB*SS*DD];          // tf32-rounded attention output
__device__ float  g_Wqkv[3*DD*DD];         // tf32-rounded [WQ;WK;WV]
__device__ float  g_Wo[DD*DD];             // tf32-rounded WO
__device__ float  g_bqkv[3*DD];
__device__ int    g_len[2*BB];             // [rowlen[b], collen[b]]

// ---------------------------------------------------------------------------
// helpers (base-target PTX: sm_80-era mma.sync + cp.async + ldmatrix)
// ---------------------------------------------------------------------------
__device__ __forceinline__ uint32_t f2tf(float f) {
    uint32_t r; asm("cvt.rna.tf32.f32 %0, %1;" : "=r"(r) : "f"(f)); return r;
}
__device__ __forceinline__ float f2tff(float f) {
    uint32_t r; asm("cvt.rna.tf32.f32 %0, %1;" : "=r"(r) : "f"(f));
    return __uint_as_float(r);
}
__device__ __forceinline__ uint32_t pack_f16x2(float lo, float hi) {
    uint32_t r;
    asm("cvt.rn.f16x2.f32 %0, %1, %2;" : "=r"(r) : "f"(hi), "f"(lo));
    return r;
}
__device__ __forceinline__ void mma_tf32(float* c, const uint32_t* a, const uint32_t* b) {
    asm volatile("mma.sync.aligned.m16n8k8.row.col.f32.tf32.tf32.f32 "
        "{%0,%1,%2,%3}, {%4,%5,%6,%7}, {%8,%9}, {%0,%1,%2,%3};"
        : "+f"(c[0]), "+f"(c[1]), "+f"(c[2]), "+f"(c[3])
        : "r"(a[0]), "r"(a[1]), "r"(a[2]), "r"(a[3]), "r"(b[0]), "r"(b[1]));
}
__device__ __forceinline__ void mma_f16(float* c, const uint32_t* a, uint32_t b0, uint32_t b1) {
    asm volatile("mma.sync.aligned.m16n8k16.row.col.f32.f16.f16.f32 "
        "{%0,%1,%2,%3}, {%4,%5,%6,%7}, {%8,%9}, {%0,%1,%2,%3};"
        : "+f"(c[0]), "+f"(c[1]), "+f"(c[2]), "+f"(c[3])
        : "r"(a[0]), "r"(a[1]), "r"(a[2]), "r"(a[3]), "r"(b0), "r"(b1));
}
__device__ __forceinline__ void ldm_x4(uint32_t& r0, uint32_t& r1, uint32_t& r2, uint32_t& r3,
                                       uint32_t addr) {
    asm volatile("ldmatrix.sync.aligned.m8n8.x4.shared.b16 {%0,%1,%2,%3}, [%4];"
        : "=r"(r0), "=r"(r1), "=r"(r2), "=r"(r3) : "r"(addr));
}
__device__ __forceinline__ void ldm_x4_t(uint32_t& r0, uint32_t& r1, uint32_t& r2, uint32_t& r3,
                                         uint32_t addr) {
    asm volatile("ldmatrix.sync.aligned.m8n8.x4.trans.shared.b16 {%0,%1,%2,%3}, [%4];"
        : "=r"(r0), "=r"(r1), "=r"(r2), "=r"(r3) : "r"(addr));
}
__device__ __forceinline__ uint32_t smem_u32(const void* p) {
    uint32_t a;
    asm("{ .reg .u64 t; cvta.to.shared.u64 t, %1; cvt.u32.u64 %0, t; }" : "=r"(a) : "l"(p));
    return a;
}
__device__ __forceinline__ void cpa16(uint32_t dst, const void* src) {
    asm volatile("cp.async.cg.shared.global [%0], [%1], 16;" :: "r"(dst), "l"(src));
}
__device__ __forceinline__ void cpa_commit() { asm volatile("cp.async.commit_group;"); }

// ---------------------------------------------------------------------------
// Prep: mask lengths + tf32 weight conversion + bias concat
// ---------------------------------------------------------------------------
__global__ void prep_kernel(const int* __restrict__ rm, const int* __restrict__ cm,
                            const float* __restrict__ WQ, const float* __restrict__ WK,
                            const float* __restrict__ WV, const float* __restrict__ WO,
                            const float* __restrict__ bQ, const float* __restrict__ bK,
                            const float* __restrict__ bV) {
    int blk = blockIdx.x, t = threadIdx.x;
    if (blk < 2) {
        __shared__ int sr[256], sc[256];
        int b = blk, r = 0, c = 0;
        for (int s = t; s < SS; s += 256) { r += rm[b*SS + s]; c += cm[b*SS + s]; }
        sr[t] = r; sc[t] = c;
        __syncthreads();
        for (int o = 128; o > 0; o >>= 1) {
            if (t < o) { sr[t] += sr[t+o]; sc[t] += sc[t+o]; }
            __syncthreads();
        }
        if (t == 0) { g_len[b] = sr[0]; g_len[BB + b] = sc[0]; }
        if (blk == 0)
            for (int i = t; i < DD; i += 256) {
                g_bqkv[i] = bQ[i]; g_bqkv[DD + i] = bK[i]; g_bqkv[2*DD + i] = bV[i];
            }
        return;
    }
    int base = (blk - 2) * 4096 + t;
    const float* srcs[4] = { WQ, WK, WV, WO };
#pragma unroll
    for (int i = 0; i < 16; i++) {
        int f4 = base + i * 256;
        int mat = f4 >> 16;
        int off = (f4 & 65535) << 2;
        float4 v = *(const float4*)(srcs[mat] + off);
        float4 o = { f2tff(v.x), f2tff(v.y), f2tff(v.z), f2tff(v.w) };
        if (mat < 3) *(float4*)(g_Wqkv + mat*DD*DD + off) = o;
        else         *(float4*)(g_Wo + off) = o;
    }
}

// ---------------------------------------------------------------------------
// tf32 GEMM, 2-stage cp.async, one sync per K-chunk. BM x 128 tile.
// EPI 0: f32 out + bias (oproj). EPI 1: fp16 per-head out (qkv).
// ---------------------------------------------------------------------------
template<int BM, bool CVT_A, int EPI>
__device__ __forceinline__ void gemm_tc(const float* __restrict__ Ag,
                                        const float* __restrict__ Wg,
                                        const float* __restrict__ bg,
                                        float* __restrict__ Cg,
                                        int bm, int bn_local, int z) {
    extern __shared__ float sg[];
    constexpr int SS_A  = BM * 36;
    constexpr int SS_AB = SS_A + 4608;
    constexpr int TM = BM / 32;
    float* bias_s = sg + 2 * SS_AB;
    const uint32_t sb = smem_u32(sg);
    const int tid = threadIdx.x;
    const int wid = tid >> 5, lane = tid & 31, gid = lane >> 2, tig = lane & 3;
    const int warp_m = wid & 1, warp_n = wid >> 1;

    if (tid < 128) bias_s[tid] = bg[tid];

    float acc[TM][4][4];
#pragma unroll
    for (int a = 0; a < TM; a++)
#pragma unroll
        for (int b = 0; b < 4; b++)
#pragma unroll
            for (int k = 0; k < 4; k++) acc[a][b][k] = 0.f;

    const int r0 = tid >> 3, c0 = (tid & 7) << 2;
    const float* pA = Ag + (size_t)(bm + r0) * DD + c0;
    const float* pB = Wg + (size_t)(bn_local + r0) * DD + c0;

#define G_LOAD(cc, buf) do { \
    uint32_t dA = sb + (uint32_t)((buf)*SS_AB + r0*36 + c0) * 4; \
    uint32_t dB = sb + (uint32_t)((buf)*SS_AB + SS_A + r0*36 + c0) * 4; \
    _Pragma("unroll") \
    for (int i = 0; i < BM/32; i++) \
        cpa16(dA + (uint32_t)i*32*36*4, pA + (size_t)i*32*DD + (cc)*32); \
    _Pragma("unroll") \
    for (int i = 0; i < 4; i++) \
        cpa16(dB + (uint32_t)i*32*36*4, pB + (size_t)i*32*DD + (cc)*32); \
} while (0)

    G_LOAD(0, 0); cpa_commit();

    for (int c = 0; c < 16; c++) {
        asm volatile("cp.async.wait_group 0;");
        __syncthreads();
        if (c + 1 < 16) { G_LOAD(c + 1, (c + 1) & 1); cpa_commit(); }

        const float* As = sg + (c & 1) * SS_AB;
        const float* Bs = As + SS_A;
#pragma unroll
        for (int ks = 0; ks < 4; ks++) {
            const int k = ks * 8 + tig;
            uint32_t af[TM][4], bf[4][2];
#pragma unroll
            for (int tm = 0; tm < TM; tm++) {
                int r = warp_m*(BM/2) + tm*16 + gid;
                if (CVT_A) {
                    af[tm][0] = f2tf(As[r*36 + k]);
                    af[tm][1] = f2tf(As[(r+8)*36 + k]);
                    af[tm][2] = f2tf(As[r*36 + k + 4]);
                    af[tm][3] = f2tf(As[(r+8)*36 + k + 4]);
                } else {
                    af[tm][0] = __float_as_uint(As[r*36 + k]);
                    af[tm][1] = __float_as_uint(As[(r+8)*36 + k]);
                    af[tm][2] = __float_as_uint(As[r*36 + k + 4]);
                    af[tm][3] = __float_as_uint(As[(r+8)*36 + k + 4]);
                }
            }
#pragma unroll
            for (int tn = 0; tn < 4; tn++) {
                int n = warp_n*32 + tn*8 + gid;
                bf[tn][0] = __float_as_uint(Bs[n*36 + k]);
                bf[tn][1] = __float_as_uint(Bs[n*36 + k + 4]);
            }
#pragma unroll
            for (int tm = 0; tm < TM; tm++)
#pragma unroll
                for (int tn = 0; tn < 4; tn++)
                    mma_tf32(acc[tm][tn], af[tm], bf[tn]);
        }
    }
#undef G_LOAD

#pragma unroll
    for (int tm = 0; tm < TM; tm++) {
        int rg = bm + warp_m*(BM/2) + tm*16 + gid;
#pragma unroll
        for (int tn = 0; tn < 4; tn++) {
            int cc = warp_n*32 + tn*8 + tig*2;
            float b0 = bias_s[cc], b1 = bias_s[cc+1];
            if (EPI == 0) {
                *(float2*)(Cg + (size_t)rg*DD + bn_local + cc) =
                    make_float2(acc[tm][tn][0] + b0, acc[tm][tn][1] + b1);
                *(float2*)(Cg + (size_t)(rg+8)*DD + bn_local + cc) =
                    make_float2(acc[tm][tn][2] + b0, acc[tm][tn][3] + b1);
            } else {
                int col = bn_local + cc;
                int h = col >> 6, d = col & 63;
#pragma unroll
                for (int rr = 0; rr < 2; rr++) {
                    int rgl = rg + rr*8;
                    int b = rgl >> 11, s = rgl & 2047;
                    uint32_t hv = pack_f16x2(acc[tm][tn][rr*2+0] + b0,
                                             acc[tm][tn][rr*2+1] + b1);
                    *(uint32_t*)(g_h16 + ((((size_t)z*BB + b)*HH + h)*SS + s)*DKK + d) = hv;
                }
            }
        }
    }
}

#define GEMM_SMEM_128 ((2*(128*36+4608) + 128)*4)
#define GEMM_SMEM_64  ((2*(64*36+4608)  + 128)*4)

__global__ void __launch_bounds__(256, 2) qkv_tc_kernel(const float* __restrict__ inQ,
                                                        const float* __restrict__ inK,
                                                        const float* __restrict__ inV) {
    int bn = blockIdx.y * 128;
    int z = bn >> 9;
    const float* A = (z == 0) ? inQ : (z == 1) ? inK : inV;
    gemm_tc<128, true, 1>(A, g_Wqkv + (size_t)z*DD*DD, g_bqkv + bn, nullptr,
                          blockIdx.x * 128, bn & 511, z);
}

__global__ void __launch_bounds__(256, 2) oproj_tc_kernel(const float* __restrict__ bO,
                                                          float* __restrict__ out) {
    gemm_tc<64, false, 0>(g_Hc, g_Wo, bO + blockIdx.y * 128, out,
                          blockIdx.x * 64, blockIdx.y * 128, 0);
}

// ---------------------------------------------------------------------------
// Flash attention v3: fp16 fragments, Br=64, 128 threads (4 warps x 16 rows).
// S = QK^T via m16n8k16.f16 (ldmatrix K, Q frags cached in regs).
// P stays in registers (m16n8k8-layout accums pack directly into A-frags).
// PV via ldmatrix.trans on V. K/V double-buffered cp.async.
// smem halfs (stride 72): Q[64][72]@0  K[2][64][72]@4608  V[2][64][72]@13824
// ---------------------------------------------------------------------------
#define HSTR 72
#define AQ 0
#define AK 4608
#define AV 13824
#define ATTN_SMEM (23040*2)

__global__ void __launch_bounds__(128, 2) attn_kernel() {
    extern __shared__ __half sah[];
    const uint32_t sb = smem_u32(sah);

    const int bh = blockIdx.z;
    const int b = bh >> 3, h = bh & 7;
    const int qt = 31 - (int)blockIdx.y;      // heavy tiles first
    const int qbase = qt << 6;
    const int rowlen = g_len[b], collen = g_len[BB + b];
    const int tid = threadIdx.x, wid = tid >> 5, lane = tid & 31;
    const int gid = lane >> 2, tig = lane & 3;
    float* Hp = g_Hc + (size_t)b*SS*DD + h*DKK;

    if (qbase >= rowlen || collen <= 0) {
#pragma unroll
        for (int i = 0; i < 8; i++) {
            int e = tid + i*128, r = e >> 4, c = (e & 15) << 2;
            *(float4*)(Hp + (size_t)(qbase + r)*DD + c) = make_float4(0.f,0.f,0.f,0.f);
        }
        return;
    }

    const __half* Qp = g_h16 + ((0*(size_t)BB + b)*HH + h)*(size_t)SS*DKK;
    const __half* Kp = g_h16 + ((1*(size_t)BB + b)*HH + h)*(size_t)SS*DKK;
    const __half* Vp = g_h16 + ((2*(size_t)BB + b)*HH + h)*(size_t)SS*DKK;

    const int kmax = min(qbase + 64, collen);
    const int nk = (kmax + 63) >> 6;

    // prologue: Q tile + K/V tile 0 in one group
#pragma unroll
    for (int i = 0; i < 4; i++) {
        int e = tid + i*128, r = e >> 3, c8 = (e & 7) << 3;
        cpa16(sb + (uint32_t)(AQ + r*HSTR + c8)*2, Qp + (size_t)(qbase + r)*DKK + c8);
    }
#define KV_LOAD(kb, s) do { \
    _Pragma("unroll") \
    for (int i = 0; i < 4; i++) { \
        int e = tid + i*128, r = e >> 3, c8 = (e & 7) << 3; \
        cpa16(sb + (uint32_t)(AK + (s)*4608 + r*HSTR + c8)*2, Kp + (size_t)((kb) + r)*DKK + c8); \
        cpa16(sb + (uint32_t)(AV + (s)*4608 + r*HSTR + c8)*2, Vp + (size_t)((kb) + r)*DKK + c8); \
    } \
} while (0)
    KV_LOAD(0, 0); cpa_commit();

    const int wr = wid * 16;
    const int q0 = qbase + wr + gid, q1 = q0 + 8;
    float m0 = -1e30f, m1 = -1e30f, l0 = 0.f, l1 = 0.f;
    float oacc[8][4];
#pragma unroll
    for (int nt = 0; nt < 8; nt++)
#pragma unroll
        for (int i = 0; i < 4; i++) oacc[nt][i] = 0.f;

    uint32_t qf[4][4];
    const int lrow = lane & 15, lcol = (lane >> 4) << 3;

    for (int kt = 0; kt < nk; kt++) {
        const int kbase = kt << 6;
        const int buf = kt & 1;
        asm volatile("cp.async.wait_group 0;");
        __syncthreads();
        if (kt == 0) {
#pragma unroll
            for (int ks = 0; ks < 4; ks++)
                ldm_x4(qf[ks][0], qf[ks][1], qf[ks][2], qf[ks][3],
                       sb + (uint32_t)(AQ + (wr + lrow)*HSTR + ks*16 + lcol)*2);
        }
        if (kt + 1 < nk) { KV_LOAD(kbase + 64, buf ^ 1); cpa_commit(); }

        const uint32_t kbuf = sb + (uint32_t)(AK + buf*4608)*2;
        const uint32_t vbuf = sb + (uint32_t)(AV + buf*4608)*2;

        // S = Q K^T
        float sacc[8][4];
#pragma unroll
        for (int nt = 0; nt < 8; nt++)
#pragma unroll
            for (int i = 0; i < 4; i++) sacc[nt][i] = 0.f;
#pragma unroll
        for (int ks = 0; ks < 4; ks++) {
#pragma unroll
            for (int nb = 0; nb < 4; nb++) {
                uint32_t r0, r1, r2, r3;
                ldm_x4(r0, r1, r2, r3,
                       kbuf + (uint32_t)((nb*16 + lrow)*HSTR + ks*16 + lcol)*2);
                mma_f16(sacc[nb*2],   qf[ks], r0, r2);
                mma_f16(sacc[nb*2+1], qf[ks], r1, r3);
            }
        }

        // scale + causal/padding mask
#pragma unroll
        for (int nt = 0; nt < 8; nt++) {
            const int kc = kbase + nt*8 + tig*2;
            sacc[nt][0] = (kc   <= q0 && q0 < rowlen && kc   < collen) ? sacc[nt][0]*0.125f : -1e30f;
            sacc[nt][1] = (kc+1 <= q0 && q0 < rowlen && kc+1 < collen) ? sacc[nt][1]*0.125f : -1e30f;
            sacc[nt][2] = (kc   <= q1 && q1 < rowlen && kc   < collen) ? sacc[nt][2]*0.125f : -1e30f;
            sacc[nt][3] = (kc+1 <= q1 && q1 < rowlen && kc+1 < collen) ? sacc[nt][3]*0.125f : -1e30f;
        }

        // warp-local row max
        float a0 = -1e30f, a1 = -1e30f;
#pragma unroll
        for (int nt = 0; nt < 8; nt++) {
            a0 = fmaxf(a0, fmaxf(sacc[nt][0], sacc[nt][1]));
            a1 = fmaxf(a1, fmaxf(sacc[nt][2], sacc[nt][3]));
        }
        a0 = fmaxf(a0, __shfl_xor_sync(0xffffffffu, a0, 1));
        a0 = fmaxf(a0, __shfl_xor_sync(0xffffffffu, a0, 2));
        a1 = fmaxf(a1, __shfl_xor_sync(0xffffffffu, a1, 1));
        a1 = fmaxf(a1, __shfl_xor_sync(0xffffffffu, a1, 2));

        const float mn0 = fmaxf(m0, a0), mn1 = fmaxf(m1, a1);
        const float sc0 = __expf(m0 - mn0), sc1 = __expf(m1 - mn1);
        l0 *= sc0; l1 *= sc1; m0 = mn0; m1 = mn1;
#pragma unroll
        for (int nt = 0; nt < 8; nt++) {
            oacc[nt][0] *= sc0; oacc[nt][1] *= sc0;
            oacc[nt][2] *= sc1; oacc[nt][3] *= sc1;
        }

        // exp in place + row sums (P stays in registers)
        float rs0 = 0.f, rs1 = 0.f;
#pragma unroll
        for (int nt = 0; nt < 8; nt++) {
            sacc[nt][0] = __expf(sacc[nt][0] - mn0);
            sacc[nt][1] = __expf(sacc[nt][1] - mn0);
            sacc[nt][2] = __expf(sacc[nt][2] - mn1);
            sacc[nt][3] = __expf(sacc[nt][3] - mn1);
            rs0 += sacc[nt][0] + sacc[nt][1];
            rs1 += sacc[nt][2] + sacc[nt][3];
        }
        rs0 += __shfl_xor_sync(0xffffffffu, rs0, 1);
        rs0 += __shfl_xor_sync(0xffffffffu, rs0, 2);
        rs1 += __shfl_xor_sync(0xffffffffu, rs1, 1);
        rs1 += __shfl_xor_sync(0xffffffffu, rs1, 2);
        l0 += rs0; l1 += rs1;

        // O += P V : A-frags packed directly from S accumulators
#pragma unroll
        for (int ks = 0; ks < 4; ks++) {
            uint32_t pa[4];
            pa[0] = pack_f16x2(sacc[2*ks][0],   sacc[2*ks][1]);
            pa[1] = pack_f16x2(sacc[2*ks][2],   sacc[2*ks][3]);
            pa[2] = pack_f16x2(sacc[2*ks+1][0], sacc[2*ks+1][1]);
            pa[3] = pack_f16x2(sacc[2*ks+1][2], sacc[2*ks+1][3]);
#pragma unroll
            for (int db = 0; db < 4; db++) {
                uint32_t v0, v1, v2, v3;
                ldm_x4_t(v0, v1, v2, v3,
                         vbuf + (uint32_t)((ks*16 + lrow)*HSTR + db*16 + lcol)*2);
                mma_f16(oacc[db*2],   pa, v0, v1);
                mma_f16(oacc[db*2+1], pa, v2, v3);
            }
        }
    }
#undef KV_LOAD

    // epilogue: normalize, tf32-round for oproj's input
    const float inv0 = (q0 < rowlen && l0 > 0.f) ? 1.f / l0 : 0.f;
    const float inv1 = (q1 < rowlen && l1 > 0.f) ? 1.f / l1 : 0.f;
#pragma unroll
    for (int nt = 0; nt < 8; nt++) {
        const int cc = nt*8 + tig*2;
        *(float2*)(Hp + (size_t)q0*DD + cc) =
            make_float2(f2tff(oacc[nt][0]*inv0), f2tff(oacc[nt][1]*inv0));
        *(float2*)(Hp + (size_t)q1*DD + cc) =
            make_float2(f2tff(oacc[nt][2]*inv1), f2tff(oacc[nt][3]*inv1));
    }
}

// ---------------------------------------------------------------------------
extern "C" void kernel_launch(void* const* d_in, const int* in_sizes, int n_in,
                              void* d_out, int out_size) {
    const float* in_Q = (const float*)d_in[0];
    const float* in_K = (const float*)d_in[1];
    const float* in_V = (const float*)d_in[2];
    const int*   rm   = (const int*)d_in[3];
    const int*   cm   = (const int*)d_in[4];
    const float* WQ = (const float*)d_in[5];  const float* bQ = (const float*)d_in[6];
    const float* WK = (const float*)d_in[7];  const float* bK = (const float*)d_in[8];
    const float* WV = (const float*)d_in[9];  const float* bV = (const float*)d_in[10];
    const float* WO = (const float*)d_in[11]; const float* bO = (const float*)d_in[12];
    float* out = (float*)d_out;

    cudaFuncSetAttribute(qkv_tc_kernel,   cudaFuncAttributeMaxDynamicSharedMemorySize, GEMM_SMEM_128);
    cudaFuncSetAttribute(oproj_tc_kernel, cudaFuncAttributeMaxDynamicSharedMemorySize, GEMM_SMEM_64);
    cudaFuncSetAttribute(attn_kernel,     cudaFuncAttributeMaxDynamicSharedMemorySize, ATTN_SMEM);

    prep_kernel<<<66, 256>>>(rm, cm, WQ, WK, WV, WO, bQ, bK, bV);

    dim3 g1(32, 12);                   // M=4096/128, N=1536/128
    qkv_tc_kernel<<<g1, 256, GEMM_SMEM_128>>>(in_Q, in_K, in_V);

    dim3 g2(1, 32, 16);                // 64-row q-tiles x (b*h), heavy-first
    attn_kernel<<<g2, 128, ATTN_SMEM>>>();

    dim3 g3(64, 4);                    // M=4096/64, N=512/128
    oproj_tc_kernel<<<g3, 256, GEMM_SMEM_64>>>(bO, out);
}

// round 8
// speedup vs baseline: 7.0363x; 1.4198x over previous
#include <cuda_runtime.h>
#include <cuda_fp16.h>
#include <cstdint>

#define BB 2
#define SS 2048
#define DD 512
#define HH 8
#define DKK 64

// Scratch (static device globals: allocation-free per harness rules)
__device__ __half g_h16[3*BB*HH*SS*DKK];   // fp16 per-head Q,K,V: [z][b][h][s][64]
__device__ __half g_inh[3*BB*SS*DD];       // fp16 activations [z][b*s][512]
__device__ __half g_Hc16[BB*SS*DD];        // fp16 attention output [b*s][512]
__device__ __half g_Wh[4*DD*DD];           // fp16 weights [WQ;WK;WV;WO], [n][k]
__device__ float  g_bqkv[3*DD];
__device__ int    g_len[2*BB];             // [rowlen[b], collen[b]]

// ---------------------------------------------------------------------------
// helpers (base-target PTX: sm_80-era mma.sync + cp.async + ldmatrix)
// ---------------------------------------------------------------------------
__device__ __forceinline__ uint32_t pack_f16x2(float lo, float hi) {
    uint32_t r;
    asm("cvt.rn.f16x2.f32 %0, %1, %2;" : "=r"(r) : "f"(hi), "f"(lo));
    return r;
}
__device__ __forceinline__ void mma_f16(float* c, const uint32_t* a, uint32_t b0, uint32_t b1) {
    asm volatile("mma.sync.aligned.m16n8k16.row.col.f32.f16.f16.f32 "
        "{%0,%1,%2,%3}, {%4,%5,%6,%7}, {%8,%9}, {%0,%1,%2,%3};"
        : "+f"(c[0]), "+f"(c[1]), "+f"(c[2]), "+f"(c[3])
        : "r"(a[0]), "r"(a[1]), "r"(a[2]), "r"(a[3]), "r"(b0), "r"(b1));
}
__device__ __forceinline__ void ldm_x4(uint32_t& r0, uint32_t& r1, uint32_t& r2, uint32_t& r3,
                                       uint32_t addr) {
    asm volatile("ldmatrix.sync.aligned.m8n8.x4.shared.b16 {%0,%1,%2,%3}, [%4];"
        : "=r"(r0), "=r"(r1), "=r"(r2), "=r"(r3) : "r"(addr));
}
__device__ __forceinline__ void ldm_x4_t(uint32_t& r0, uint32_t& r1, uint32_t& r2, uint32_t& r3,
                                         uint32_t addr) {
    asm volatile("ldmatrix.sync.aligned.m8n8.x4.trans.shared.b16 {%0,%1,%2,%3}, [%4];"
        : "=r"(r0), "=r"(r1), "=r"(r2), "=r"(r3) : "r"(addr));
}
__device__ __forceinline__ uint32_t smem_u32(const void* p) {
    uint32_t a;
    asm("{ .reg .u64 t; cvta.to.shared.u64 t, %1; cvt.u32.u64 %0, t; }" : "=r"(a) : "l"(p));
    return a;
}
__device__ __forceinline__ void cpa16(uint32_t dst, const void* src) {
    asm volatile("cp.async.cg.shared.global [%0], [%1], 16;" :: "r"(dst), "l"(src));
}
__device__ __forceinline__ void cpa_commit() { asm volatile("cp.async.commit_group;"); }

// ---------------------------------------------------------------------------
// Prep: mask lengths + bias concat + fp16 conversion of weights & activations
// blocks 0,1: masklen; 2..65: weights (4x512x512); 66..321: activations
// ---------------------------------------------------------------------------
__global__ void prep_kernel(const int* __restrict__ rm, const int* __restrict__ cm,
                            const float* __restrict__ WQ, const float* __restrict__ WK,
                            const float* __restrict__ WV, const float* __restrict__ WO,
                            const float* __restrict__ bQ, const float* __restrict__ bK,
                            const float* __restrict__ bV,
                            const float* __restrict__ inQ, const float* __restrict__ inK,
                            const float* __restrict__ inV) {
    int blk = blockIdx.x, t = threadIdx.x;
    if (blk < 2) {
        __shared__ int sr[256], sc[256];
        int b = blk, r = 0, c = 0;
        for (int s = t; s < SS; s += 256) { r += rm[b*SS + s]; c += cm[b*SS + s]; }
        sr[t] = r; sc[t] = c;
        __syncthreads();
        for (int o = 128; o > 0; o >>= 1) {
            if (t < o) { sr[t] += sr[t+o]; sc[t] += sc[t+o]; }
            __syncthreads();
        }
        if (t == 0) { g_len[b] = sr[0]; g_len[BB + b] = sc[0]; }
        if (blk == 0)
            for (int i = t; i < DD; i += 256) {
                g_bqkv[i] = bQ[i]; g_bqkv[DD + i] = bK[i]; g_bqkv[2*DD + i] = bV[i];
            }
        return;
    }
    if (blk < 66) {
        // weights: 4 x 65536 float4 -> fp16
        int base = (blk - 2) * 4096 + t;
        const float* srcs[4] = { WQ, WK, WV, WO };
#pragma unroll
        for (int i = 0; i < 16; i++) {
            int f4 = base + i * 256;
            int mat = f4 >> 16;
            int off = (f4 & 65535) << 2;
            float4 v = *(const float4*)(srcs[mat] + off);
            uint2 u = { pack_f16x2(v.x, v.y), pack_f16x2(v.z, v.w) };
            *(uint2*)(g_Wh + (size_t)mat*DD*DD + off) = u;
        }
        return;
    }
    // activations: 3 x 524288 float4 -> fp16
    int base = (blk - 66) * 256 + t;
#pragma unroll
    for (int i = 0; i < 24; i++) {
        int f4 = base + i * 65536;
        int tsr = f4 / 524288;
        int off = (f4 - tsr * 524288) << 2;
        const float* s = (tsr == 0) ? inQ : (tsr == 1) ? inK : inV;
        float4 v = *(const float4*)(s + off);
        uint2 u = { pack_f16x2(v.x, v.y), pack_f16x2(v.z, v.w) };
        *(uint2*)(g_inh + (size_t)tsr*BB*SS*DD + off) = u;
    }
}

// ---------------------------------------------------------------------------
// fp16 GEMM (m16n8k16 + ldmatrix), 2-stage cp.async, one sync per K-chunk.
// BM x 128 tile, K chunks of 32. 256 threads, 8 warps; warp tile (BM/2) x 32.
// smem stride 40 halfs (80B): ldmatrix phases hit all 32 banks exactly once.
// EPI 0: f32 out + bias (oproj). EPI 1: fp16 per-head out (qkv).
// ---------------------------------------------------------------------------
#define GSTR 40

template<int BM, int EPI>
__device__ __forceinline__ void gemm_f16(const __half* __restrict__ Ag,
                                         const __half* __restrict__ Wg,
                                         const float* __restrict__ bg,
                                         float* __restrict__ Cg,
                                         int bm, int bn_local, int z) {
    extern __shared__ __half sh[];
    constexpr int SS_A  = BM * GSTR;
    constexpr int SS_AB = SS_A + 128 * GSTR;
    constexpr int TM = BM / 32;
    float* bias_s = (float*)(sh + 2 * SS_AB);
    const uint32_t sb = smem_u32(sh);
    const int tid = threadIdx.x;
    const int wid = tid >> 5, lane = tid & 31, gid = lane >> 2, tig = lane & 3;
    const int warp_m = wid & 1, warp_n = wid >> 1;
    const int lrow = lane & 15, lcol = (lane >> 4) << 3;

    if (tid < 128) bias_s[tid] = bg[tid];

    float acc[TM][4][4];
#pragma unroll
    for (int a = 0; a < TM; a++)
#pragma unroll
        for (int b = 0; b < 4; b++)
#pragma unroll
            for (int k = 0; k < 4; k++) acc[a][b][k] = 0.f;

    const int r0 = tid >> 2, c0 = (tid & 3) << 3;      // halfs
    const __half* pA = Ag + (size_t)(bm + r0) * DD + c0;
    const __half* pB = Wg + (size_t)(bn_local + r0) * DD + c0;

#define G_LOAD(cc, buf) do { \
    _Pragma("unroll") \
    for (int i = 0; i < BM/64; i++) \
        cpa16(sb + (uint32_t)((buf)*SS_AB + (i*64 + r0)*GSTR + c0)*2, \
              pA + (size_t)i*64*DD + (cc)*32); \
    _Pragma("unroll") \
    for (int i = 0; i < 2; i++) \
        cpa16(sb + (uint32_t)((buf)*SS_AB + SS_A + (i*64 + r0)*GSTR + c0)*2, \
              pB + (size_t)i*64*DD + (cc)*32); \
    cpa_commit(); \
} while (0)

    G_LOAD(0, 0);

    for (int c = 0; c < 16; c++) {
        asm volatile("cp.async.wait_group 0;");
        __syncthreads();
        if (c + 1 < 16) G_LOAD(c + 1, (c + 1) & 1);

        const uint32_t abase = sb + (uint32_t)((c & 1) * SS_AB) * 2;
        const uint32_t bbase = abase + (uint32_t)SS_A * 2;
#pragma unroll
        for (int ks = 0; ks < 2; ks++) {
            uint32_t af[TM][4];
#pragma unroll
            for (int mt = 0; mt < TM; mt++)
                ldm_x4(af[mt][0], af[mt][1], af[mt][2], af[mt][3],
                       abase + (uint32_t)((warp_m*(BM/2) + mt*16 + lrow)*GSTR + ks*16 + lcol)*2);
#pragma unroll
            for (int ns = 0; ns < 2; ns++) {
                uint32_t b0, b1, b2, b3;
                ldm_x4(b0, b1, b2, b3,
                       bbase + (uint32_t)((warp_n*32 + ns*16 + lrow)*GSTR + ks*16 + lcol)*2);
#pragma unroll
                for (int mt = 0; mt < TM; mt++) {
                    mma_f16(acc[mt][ns*2],   af[mt], b0, b2);
                    mma_f16(acc[mt][ns*2+1], af[mt], b1, b3);
                }
            }
        }
    }
#undef G_LOAD

#pragma unroll
    for (int mt = 0; mt < TM; mt++) {
        int rg = bm + warp_m*(BM/2) + mt*16 + gid;
#pragma unroll
        for (int tn = 0; tn < 4; tn++) {
            int cc = warp_n*32 + tn*8 + tig*2;
            float b0 = bias_s[cc], b1 = bias_s[cc+1];
            if (EPI == 0) {
                *(float2*)(Cg + (size_t)rg*DD + bn_local + cc) =
                    make_float2(acc[mt][tn][0] + b0, acc[mt][tn][1] + b1);
                *(float2*)(Cg + (size_t)(rg+8)*DD + bn_local + cc) =
                    make_float2(acc[mt][tn][2] + b0, acc[mt][tn][3] + b1);
            } else {
                int col = bn_local + cc;
                int h = col >> 6, d = col & 63;
#pragma unroll
                for (int rr = 0; rr < 2; rr++) {
                    int rgl = rg + rr*8;
                    int b = rgl >> 11, s = rgl & 2047;
                    uint32_t hv = pack_f16x2(acc[mt][tn][rr*2+0] + b0,
                                             acc[mt][tn][rr*2+1] + b1);
                    *(uint32_t*)(g_h16 + ((((size_t)z*BB + b)*HH + h)*SS + s)*DKK + d) = hv;
                }
            }
        }
    }
}

#define GEMM_SMEM_128 (2*(128*GSTR + 128*GSTR)*2 + 512)
#define GEMM_SMEM_64  (2*(64*GSTR  + 128*GSTR)*2 + 512)

__global__ void __launch_bounds__(256, 2) qkv_tc_kernel() {
    int bn = blockIdx.y * 128;
    int z = bn >> 9;
    gemm_f16<128, 1>(g_inh + (size_t)z*BB*SS*DD, g_Wh + (size_t)z*DD*DD,
                     g_bqkv + bn, nullptr, blockIdx.x * 128, bn & 511, z);
}

__global__ void __launch_bounds__(256, 2) oproj_tc_kernel(const float* __restrict__ bO,
                                                          float* __restrict__ out) {
    gemm_f16<64, 0>(g_Hc16, g_Wh + 3*(size_t)DD*DD, bO + blockIdx.y * 128, out,
                    blockIdx.x * 64, blockIdx.y * 128, 0);
}

// ---------------------------------------------------------------------------
// Flash attention (fp16 fragments), Br=64, 128 threads (4 warps x 16 rows).
// smem halfs (stride 72): Q[64][72]@0  K[2][64][72]@4608  V[2][64][72]@13824
// ---------------------------------------------------------------------------
#define HSTR 72
#define AQ 0
#define AK 4608
#define AV 13824
#define ATTN_SMEM (23040*2)

__global__ void __launch_bounds__(128, 3) attn_kernel() {
    extern __shared__ __half sah[];
    const uint32_t sb = smem_u32(sah);

    const int bh = blockIdx.z;
    const int b = bh >> 3, h = bh & 7;
    const int qt = 31 - (int)blockIdx.y;      // heavy tiles first
    const int qbase = qt << 6;
    const int rowlen = g_len[b], collen = g_len[BB + b];
    const int tid = threadIdx.x, wid = tid >> 5, lane = tid & 31;
    const int gid = lane >> 2, tig = lane & 3;
    __half* Hp = g_Hc16 + (size_t)b*SS*DD + h*DKK;

    if (qbase >= rowlen || collen <= 0) {
#pragma unroll
        for (int i = 0; i < 8; i++) {
            int e = tid + i*128, r = e >> 4, c = (e & 15) << 2;
            *(uint2*)(Hp + (size_t)(qbase + r)*DD + c) = make_uint2(0u, 0u);
        }
        return;
    }

    const __half* Qp = g_h16 + ((0*(size_t)BB + b)*HH + h)*(size_t)SS*DKK;
    const __half* Kp = g_h16 + ((1*(size_t)BB + b)*HH + h)*(size_t)SS*DKK;
    const __half* Vp = g_h16 + ((2*(size_t)BB + b)*HH + h)*(size_t)SS*DKK;

    const int kmax = min(qbase + 64, collen);
    const int nk = (kmax + 63) >> 6;

#pragma unroll
    for (int i = 0; i < 4; i++) {
        int e = tid + i*128, r = e >> 3, c8 = (e & 7) << 3;
        cpa16(sb + (uint32_t)(AQ + r*HSTR + c8)*2, Qp + (size_t)(qbase + r)*DKK + c8);
    }
#define KV_LOAD(kb, s) do { \
    _Pragma("unroll") \
    for (int i = 0; i < 4; i++) { \
        int e = tid + i*128, r = e >> 3, c8 = (e & 7) << 3; \
        cpa16(sb + (uint32_t)(AK + (s)*4608 + r*HSTR + c8)*2, Kp + (size_t)((kb) + r)*DKK + c8); \
        cpa16(sb + (uint32_t)(AV + (s)*4608 + r*HSTR + c8)*2, Vp + (size_t)((kb) + r)*DKK + c8); \
    } \
} while (0)
    KV_LOAD(0, 0); cpa_commit();

    const int wr = wid * 16;
    const int q0 = qbase + wr + gid, q1 = q0 + 8;
    float m0 = -1e30f, m1 = -1e30f, l0 = 0.f, l1 = 0.f;
    float oacc[8][4];
#pragma unroll
    for (int nt = 0; nt < 8; nt++)
#pragma unroll
        for (int i = 0; i < 4; i++) oacc[nt][i] = 0.f;

    uint32_t qf[4][4];
    const int lrow = lane & 15, lcol = (lane >> 4) << 3;

    for (int kt = 0; kt < nk; kt++) {
        const int kbase = kt << 6;
        const int buf = kt & 1;
        asm volatile("cp.async.wait_group 0;");
        __syncthreads();
        if (kt == 0) {
#pragma unroll
            for (int ks = 0; ks < 4; ks++)
                ldm_x4(qf[ks][0], qf[ks][1], qf[ks][2], qf[ks][3],
                       sb + (uint32_t)(AQ + (wr + lrow)*HSTR + ks*16 + lcol)*2);
        }
        if (kt + 1 < nk) { KV_LOAD(kbase + 64, buf ^ 1); cpa_commit(); }

        const uint32_t kbuf = sb + (uint32_t)(AK + buf*4608)*2;
        const uint32_t vbuf = sb + (uint32_t)(AV + buf*4608)*2;

        float sacc[8][4];
#pragma unroll
        for (int nt = 0; nt < 8; nt++)
#pragma unroll
            for (int i = 0; i < 4; i++) sacc[nt][i] = 0.f;
#pragma unroll
        for (int ks = 0; ks < 4; ks++) {
#pragma unroll
            for (int nb = 0; nb < 4; nb++) {
                uint32_t r0, r1, r2, r3;
                ldm_x4(r0, r1, r2, r3,
                       kbuf + (uint32_t)((nb*16 + lrow)*HSTR + ks*16 + lcol)*2);
                mma_f16(sacc[nb*2],   qf[ks], r0, r2);
                mma_f16(sacc[nb*2+1], qf[ks], r1, r3);
            }
        }

#pragma unroll
        for (int nt = 0; nt < 8; nt++) {
            const int kc = kbase + nt*8 + tig*2;
            sacc[nt][0] = (kc   <= q0 && q0 < rowlen && kc   < collen) ? sacc[nt][0]*0.125f : -1e30f;
            sacc[nt][1] = (kc+1 <= q0 && q0 < rowlen && kc+1 < collen) ? sacc[nt][1]*0.125f : -1e30f;
            sacc[nt][2] = (kc   <= q1 && q1 < rowlen && kc   < collen) ? sacc[nt][2]*0.125f : -1e30f;
            sacc[nt][3] = (kc+1 <= q1 && q1 < rowlen && kc+1 < collen) ? sacc[nt][3]*0.125f : -1e30f;
        }

        float a0 = -1e30f, a1 = -1e30f;
#pragma unroll
        for (int nt = 0; nt < 8; nt++) {
            a0 = fmaxf(a0, fmaxf(sacc[nt][0], sacc[nt][1]));
            a1 = fmaxf(a1, fmaxf(sacc[nt][2], sacc[nt][3]));
        }
        a0 = fmaxf(a0, __shfl_xor_sync(0xffffffffu, a0, 1));
        a0 = fmaxf(a0, __shfl_xor_sync(0xffffffffu, a0, 2));
        a1 = fmaxf(a1, __shfl_xor_sync(0xffffffffu, a1, 1));
        a1 = fmaxf(a1, __shfl_xor_sync(0xffffffffu, a1, 2));

        const float mn0 = fmaxf(m0, a0), mn1 = fmaxf(m1, a1);
        const float sc0 = __expf(m0 - mn0), sc1 = __expf(m1 - mn1);
        l0 *= sc0; l1 *= sc1; m0 = mn0; m1 = mn1;
#pragma unroll
        for (int nt = 0; nt < 8; nt++) {
            oacc[nt][0] *= sc0; oacc[nt][1] *= sc0;
            oacc[nt][2] *= sc1; oacc[nt][3] *= sc1;
        }

        float rs0 = 0.f, rs1 = 0.f;
#pragma unroll
        for (int nt = 0; nt < 8; nt++) {
            sacc[nt][0] = __expf(sacc[nt][0] - mn0);
            sacc[nt][1] = __expf(sacc[nt][1] - mn0);
            sacc[nt][2] = __expf(sacc[nt][2] - mn1);
            sacc[nt][3] = __expf(sacc[nt][3] - mn1);
            rs0 += sacc[nt][0] + sacc[nt][1];
            rs1 += sacc[nt][2] + sacc[nt][3];
        }
        rs0 += __shfl_xor_sync(0xffffffffu, rs0, 1);
        rs0 += __shfl_xor_sync(0xffffffffu, rs0, 2);
        rs1 += __shfl_xor_sync(0xffffffffu, rs1, 1);
        rs1 += __shfl_xor_sync(0xffffffffu, rs1, 2);
        l0 += rs0; l1 += rs1;

#pragma unroll
        for (int ks = 0; ks < 4; ks++) {
            uint32_t pa[4];
            pa[0] = pack_f16x2(sacc[2*ks][0],   sacc[2*ks][1]);
            pa[1] = pack_f16x2(sacc[2*ks][2],   sacc[2*ks][3]);
            pa[2] = pack_f16x2(sacc[2*ks+1][0], sacc[2*ks+1][1]);
            pa[3] = pack_f16x2(sacc[2*ks+1][2], sacc[2*ks+1][3]);
#pragma unroll
            for (int db = 0; db < 4; db++) {
                uint32_t v0, v1, v2, v3;
                ldm_x4_t(v0, v1, v2, v3,
                         vbuf + (uint32_t)((ks*16 + lrow)*HSTR + db*16 + lcol)*2);
                mma_f16(oacc[db*2],   pa, v0, v1);
                mma_f16(oacc[db*2+1], pa, v2, v3);
            }
        }
    }
#undef KV_LOAD

    // epilogue: normalize, write fp16 Hc (oproj consumes fp16 A)
    const float inv0 = (q0 < rowlen && l0 > 0.f) ? 1.f / l0 : 0.f;
    const float inv1 = (q1 < rowlen && l1 > 0.f) ? 1.f / l1 : 0.f;
#pragma unroll
    for (int nt = 0; nt < 8; nt++) {
        const int cc = nt*8 + tig*2;
        *(uint32_t*)(Hp + (size_t)q0*DD + cc) = pack_f16x2(oacc[nt][0]*inv0, oacc[nt][1]*inv0);
        *(uint32_t*)(Hp + (size_t)q1*DD + cc) = pack_f16x2(oacc[nt][2]*inv1, oacc[nt][3]*inv1);
    }
}

// ---------------------------------------------------------------------------
extern "C" void kernel_launch(void* const* d_in, const int* in_sizes, int n_in,
                              void* d_out, int out_size) {
    const float* in_Q = (const float*)d_in[0];
    const float* in_K = (const float*)d_in[1];
    const float* in_V = (const float*)d_in[2];
    const int*   rm   = (const int*)d_in[3];
    const int*   cm   = (const int*)d_in[4];
    const float* WQ = (const float*)d_in[5];  const float* bQ = (const float*)d_in[6];
    const float* WK = (const float*)d_in[7];  const float* bK = (const float*)d_in[8];
    const float* WV = (const float*)d_in[9];  const float* bV = (const float*)d_in[10];
    const float* WO = (const float*)d_in[11]; const float* bO = (const float*)d_in[12];
    float* out = (float*)d_out;

    cudaFuncSetAttribute(qkv_tc_kernel,   cudaFuncAttributeMaxDynamicSharedMemorySize, GEMM_SMEM_128);
    cudaFuncSetAttribute(oproj_tc_kernel, cudaFuncAttributeMaxDynamicSharedMemorySize, GEMM_SMEM_64);
    cudaFuncSetAttribute(attn_kernel,     cudaFuncAttributeMaxDynamicSharedMemorySize, ATTN_SMEM);

    prep_kernel<<<322, 256>>>(rm, cm, WQ, WK, WV, WO, bQ, bK, bV, in_Q, in_K, in_V);

    dim3 g1(32, 12);                   // M=4096/128, N=1536/128
    qkv_tc_kernel<<<g1, 256, GEMM_SMEM_128>>>();

    dim3 g2(1, 32, 16);                // 64-row q-tiles x (b*h), heavy-first
    attn_kernel<<<g2, 128, ATTN_SMEM>>>();

    dim3 g3(64, 4);                    // M=4096/64, N=512/128
    oproj_tc_kernel<<<g3, 256, GEMM_SMEM_64>>>(bO, out);
}

// round 9
// speedup vs baseline: 8.1277x; 1.1551x over previous
#include <cuda_runtime.h>
#include <cuda_fp16.h>
#include <cstdint>

#define BB 2
#define SS 2048
#define DD 512
#define HH 8
#define DKK 64

// Scratch (static device globals: allocation-free per harness rules)
__device__ __half g_h16[3*BB*HH*SS*DKK];   // fp16 per-head Q,K,V: [z][b][h][s][64]
__device__ __half g_inh[3*BB*SS*DD];       // fp16 activations [z][b*s][512]
__device__ __half g_Hc16[BB*SS*DD];        // fp16 attention output [b*s][512]
__device__ __half g_Wh[4*DD*DD];           // fp16 weights [WQ;WK;WV;WO], [n][k]
__device__ float  g_bqkv[3*DD];
__device__ int    g_len[2*BB];             // [rowlen[b], collen[b]]

// ---------------------------------------------------------------------------
// helpers (base-target PTX: sm_80-era mma.sync + cp.async + ldmatrix)
// ---------------------------------------------------------------------------
__device__ __forceinline__ uint32_t pack_f16x2(float lo, float hi) {
    uint32_t r;
    asm("cvt.rn.f16x2.f32 %0, %1, %2;" : "=r"(r) : "f"(hi), "f"(lo));
    return r;
}
__device__ __forceinline__ void mma_f16(float* c, const uint32_t* a, uint32_t b0, uint32_t b1) {
    asm volatile("mma.sync.aligned.m16n8k16.row.col.f32.f16.f16.f32 "
        "{%0,%1,%2,%3}, {%4,%5,%6,%7}, {%8,%9}, {%0,%1,%2,%3};"
        : "+f"(c[0]), "+f"(c[1]), "+f"(c[2]), "+f"(c[3])
        : "r"(a[0]), "r"(a[1]), "r"(a[2]), "r"(a[3]), "r"(b0), "r"(b1));
}
__device__ __forceinline__ void ldm_x4(uint32_t& r0, uint32_t& r1, uint32_t& r2, uint32_t& r3,
                                       uint32_t addr) {
    asm volatile("ldmatrix.sync.aligned.m8n8.x4.shared.b16 {%0,%1,%2,%3}, [%4];"
        : "=r"(r0), "=r"(r1), "=r"(r2), "=r"(r3) : "r"(addr));
}
__device__ __forceinline__ void ldm_x4_t(uint32_t& r0, uint32_t& r1, uint32_t& r2, uint32_t& r3,
                                         uint32_t addr) {
    asm volatile("ldmatrix.sync.aligned.m8n8.x4.trans.shared.b16 {%0,%1,%2,%3}, [%4];"
        : "=r"(r0), "=r"(r1), "=r"(r2), "=r"(r3) : "r"(addr));
}
__device__ __forceinline__ uint32_t smem_u32(const void* p) {
    uint32_t a;
    asm("{ .reg .u64 t; cvta.to.shared.u64 t, %1; cvt.u32.u64 %0, t; }" : "=r"(a) : "l"(p));
    return a;
}
__device__ __forceinline__ void cpa16(uint32_t dst, const void* src) {
    asm volatile("cp.async.cg.shared.global [%0], [%1], 16;" :: "r"(dst), "l"(src));
}
__device__ __forceinline__ void cpa_commit() { asm volatile("cp.async.commit_group;"); }

// ---------------------------------------------------------------------------
// Prep: mask lengths + bias concat + fp16 conversion of weights & activations
// ---------------------------------------------------------------------------
__global__ void prep_kernel(const int* __restrict__ rm, const int* __restrict__ cm,
                            const float* __restrict__ WQ, const float* __restrict__ WK,
                            const float* __restrict__ WV, const float* __restrict__ WO,
                            const float* __restrict__ bQ, const float* __restrict__ bK,
                            const float* __restrict__ bV,
                            const float* __restrict__ inQ, const float* __restrict__ inK,
                            const float* __restrict__ inV) {
    int blk = blockIdx.x, t = threadIdx.x;
    if (blk < 2) {
        __shared__ int sr[256], sc[256];
        int b = blk, r = 0, c = 0;
        for (int s = t; s < SS; s += 256) { r += rm[b*SS + s]; c += cm[b*SS + s]; }
        sr[t] = r; sc[t] = c;
        __syncthreads();
        for (int o = 128; o > 0; o >>= 1) {
            if (t < o) { sr[t] += sr[t+o]; sc[t] += sc[t+o]; }
            __syncthreads();
        }
        if (t == 0) { g_len[b] = sr[0]; g_len[BB + b] = sc[0]; }
        if (blk == 0)
            for (int i = t; i < DD; i += 256) {
                g_bqkv[i] = bQ[i]; g_bqkv[DD + i] = bK[i]; g_bqkv[2*DD + i] = bV[i];
            }
        return;
    }
    if (blk < 66) {
        int base = (blk - 2) * 4096 + t;
        const float* srcs[4] = { WQ, WK, WV, WO };
#pragma unroll
        for (int i = 0; i < 16; i++) {
            int f4 = base + i * 256;
            int mat = f4 >> 16;
            int off = (f4 & 65535) << 2;
            float4 v = *(const float4*)(srcs[mat] + off);
            uint2 u = { pack_f16x2(v.x, v.y), pack_f16x2(v.z, v.w) };
            *(uint2*)(g_Wh + (size_t)mat*DD*DD + off) = u;
        }
        return;
    }
    int base = (blk - 66) * 256 + t;
#pragma unroll
    for (int i = 0; i < 24; i++) {
        int f4 = base + i * 65536;
        int tsr = f4 / 524288;
        int off = (f4 - tsr * 524288) << 2;
        const float* s = (tsr == 0) ? inQ : (tsr == 1) ? inK : inV;
        float4 v = *(const float4*)(s + off);
        uint2 u = { pack_f16x2(v.x, v.y), pack_f16x2(v.z, v.w) };
        *(uint2*)(g_inh + (size_t)tsr*BB*SS*DD + off) = u;
    }
}

// ---------------------------------------------------------------------------
// fp16 GEMM (m16n8k16 + ldmatrix), 4-stage cp.async, wait_group 2.
// BM x 128 tile, K chunks of 32. 256 threads, 8 warps; warp tile (BM/2) x 32.
// Exactly one commit group per iteration (empty at tail) keeps counting exact.
// ---------------------------------------------------------------------------
#define GSTR 40

template<int BM, int EPI>
__device__ __forceinline__ void gemm_f16(const __half* __restrict__ Ag,
                                         const __half* __restrict__ Wg,
                                         const float* __restrict__ bg,
                                         float* __restrict__ Cg,
                                         int bm, int bn_local, int z) {
    extern __shared__ __half sh[];
    constexpr int SS_A  = BM * GSTR;
    constexpr int SS_AB = SS_A + 128 * GSTR;
    constexpr int TM = BM / 32;
    float* bias_s = (float*)(sh + 4 * SS_AB);
    const uint32_t sb = smem_u32(sh);
    const int tid = threadIdx.x;
    const int wid = tid >> 5, lane = tid & 31, gid = lane >> 2, tig = lane & 3;
    const int warp_m = wid & 1, warp_n = wid >> 1;
    const int lrow = lane & 15, lcol = (lane >> 4) << 3;

    if (tid < 128) bias_s[tid] = bg[tid];

    float acc[TM][4][4];
#pragma unroll
    for (int a = 0; a < TM; a++)
#pragma unroll
        for (int b = 0; b < 4; b++)
#pragma unroll
            for (int k = 0; k < 4; k++) acc[a][b][k] = 0.f;

    const int r0 = tid >> 2, c0 = (tid & 3) << 3;      // halfs
    const __half* pA = Ag + (size_t)(bm + r0) * DD + c0;
    const __half* pB = Wg + (size_t)(bn_local + r0) * DD + c0;

#define G_LOAD(cc, buf) do { \
    _Pragma("unroll") \
    for (int i = 0; i < BM/64; i++) \
        cpa16(sb + (uint32_t)((buf)*SS_AB + (i*64 + r0)*GSTR + c0)*2, \
              pA + (size_t)i*64*DD + (cc)*32); \
    _Pragma("unroll") \
    for (int i = 0; i < 2; i++) \
        cpa16(sb + (uint32_t)((buf)*SS_AB + SS_A + (i*64 + r0)*GSTR + c0)*2, \
              pB + (size_t)i*64*DD + (cc)*32); \
    cpa_commit(); \
} while (0)

    G_LOAD(0, 0); G_LOAD(1, 1); G_LOAD(2, 2);

    for (int c = 0; c < 16; c++) {
        asm volatile("cp.async.wait_group 2;");
        __syncthreads();
        if (c + 3 < 16) G_LOAD(c + 3, (c + 3) & 3); else cpa_commit();

        const uint32_t abase = sb + (uint32_t)((c & 3) * SS_AB) * 2;
        const uint32_t bbase = abase + (uint32_t)SS_A * 2;
#pragma unroll
        for (int ks = 0; ks < 2; ks++) {
            uint32_t af[TM][4];
#pragma unroll
            for (int mt = 0; mt < TM; mt++)
                ldm_x4(af[mt][0], af[mt][1], af[mt][2], af[mt][3],
                       abase + (uint32_t)((warp_m*(BM/2) + mt*16 + lrow)*GSTR + ks*16 + lcol)*2);
#pragma unroll
            for (int ns = 0; ns < 2; ns++) {
                uint32_t b0, b1, b2, b3;
                ldm_x4(b0, b1, b2, b3,
                       bbase + (uint32_t)((warp_n*32 + ns*16 + lrow)*GSTR + ks*16 + lcol)*2);
#pragma unroll
                for (int mt = 0; mt < TM; mt++) {
                    mma_f16(acc[mt][ns*2],   af[mt], b0, b2);
                    mma_f16(acc[mt][ns*2+1], af[mt], b1, b3);
                }
            }
        }
    }
#undef G_LOAD

#pragma unroll
    for (int mt = 0; mt < TM; mt++) {
        int rg = bm + warp_m*(BM/2) + mt*16 + gid;
#pragma unroll
        for (int tn = 0; tn < 4; tn++) {
            int cc = warp_n*32 + tn*8 + tig*2;
            float b0 = bias_s[cc], b1 = bias_s[cc+1];
            if (EPI == 0) {
                *(float2*)(Cg + (size_t)rg*DD + bn_local + cc) =
                    make_float2(acc[mt][tn][0] + b0, acc[mt][tn][1] + b1);
                *(float2*)(Cg + (size_t)(rg+8)*DD + bn_local + cc) =
                    make_float2(acc[mt][tn][2] + b0, acc[mt][tn][3] + b1);
            } else {
                int col = bn_local + cc;
                int h = col >> 6, d = col & 63;
#pragma unroll
                for (int rr = 0; rr < 2; rr++) {
                    int rgl = rg + rr*8;
                    int b = rgl >> 11, s = rgl & 2047;
                    uint32_t hv = pack_f16x2(acc[mt][tn][rr*2+0] + b0,
                                             acc[mt][tn][rr*2+1] + b1);
                    *(uint32_t*)(g_h16 + ((((size_t)z*BB + b)*HH + h)*SS + s)*DKK + d) = hv;
                }
            }
        }
    }
}

#define GEMM_SMEM_128 (4*(128*GSTR + 128*GSTR)*2 + 512)
#define GEMM_SMEM_64  (4*(64*GSTR  + 128*GSTR)*2 + 512)

// QKV with dead-row CTA skip: rows >= ceil(max(rl,cl)/64)*64 are never read.
__global__ void __launch_bounds__(256, 2) qkv_tc_kernel() {
    int bm = blockIdx.x * 128;
    int b = bm >> 11, s_start = bm & 2047;
    int need = max(g_len[b], g_len[BB + b]);
    need = (need + 63) & ~63;
    if (s_start >= need) return;
    int bn = blockIdx.y * 128;
    int z = bn >> 9;
    gemm_f16<128, 1>(g_inh + (size_t)z*BB*SS*DD, g_Wh + (size_t)z*DD*DD,
                     g_bqkv + bn, nullptr, bm, bn & 511, z);
}

// O projection with bias fast path: rows >= rowlen have Hc==0 -> out = b_O.
__global__ void __launch_bounds__(256, 2) oproj_tc_kernel(const float* __restrict__ bO,
                                                          float* __restrict__ out) {
    int bm = blockIdx.x * 64;
    int b = bm >> 11, s_start = bm & 2047;
    int rl = g_len[b];
    const float* bg = bO + blockIdx.y * 128;
    if (s_start >= rl) {
#pragma unroll
        for (int i = 0; i < 8; i++) {
            int idx = threadIdx.x + i*256;
            int r = idx >> 5, cf = (idx & 31) << 2;
            float4 bv = *(const float4*)(bg + cf);
            *(float4*)(out + (size_t)(bm + r)*DD + blockIdx.y*128 + cf) = bv;
        }
        return;
    }
    gemm_f16<64, 0>(g_Hc16, g_Wh + 3*(size_t)DD*DD, bg, out,
                    bm, blockIdx.y * 128, 0);
}

// ---------------------------------------------------------------------------
// Flash attention (fp16 fragments), Br=64, 128 threads (4 warps x 16 rows).
// smem halfs (stride 72): Q[64][72]@0  K[2][64][72]@4608  V[2][64][72]@13824
// ---------------------------------------------------------------------------
#define HSTR 72
#define AQ 0
#define AK 4608
#define AV 13824
#define ATTN_SMEM (23040*2)

__global__ void __launch_bounds__(128, 3) attn_kernel() {
    extern __shared__ __half sah[];
    const uint32_t sb = smem_u32(sah);

    const int bh = blockIdx.z;
    const int b = bh >> 3, h = bh & 7;
    const int qt = 31 - (int)blockIdx.y;      // heavy tiles first
    const int qbase = qt << 6;
    const int rowlen = g_len[b], collen = g_len[BB + b];
    const int tid = threadIdx.x, wid = tid >> 5, lane = tid & 31;
    const int gid = lane >> 2, tig = lane & 3;
    __half* Hp = g_Hc16 + (size_t)b*SS*DD + h*DKK;

    if (qbase >= rowlen || collen <= 0) {
#pragma unroll
        for (int i = 0; i < 8; i++) {
            int e = tid + i*128, r = e >> 4, c = (e & 15) << 2;
            *(uint2*)(Hp + (size_t)(qbase + r)*DD + c) = make_uint2(0u, 0u);
        }
        return;
    }

    const __half* Qp = g_h16 + ((0*(size_t)BB + b)*HH + h)*(size_t)SS*DKK;
    const __half* Kp = g_h16 + ((1*(size_t)BB + b)*HH + h)*(size_t)SS*DKK;
    const __half* Vp = g_h16 + ((2*(size_t)BB + b)*HH + h)*(size_t)SS*DKK;

    const int kmax = min(qbase + 64, collen);
    const int nk = (kmax + 63) >> 6;

#pragma unroll
    for (int i = 0; i < 4; i++) {
        int e = tid + i*128, r = e >> 3, c8 = (e & 7) << 3;
        cpa16(sb + (uint32_t)(AQ + r*HSTR + c8)*2, Qp + (size_t)(qbase + r)*DKK + c8);
    }
#define KV_LOAD(kb, s) do { \
    _Pragma("unroll") \
    for (int i = 0; i < 4; i++) { \
        int e = tid + i*128, r = e >> 3, c8 = (e & 7) << 3; \
        cpa16(sb + (uint32_t)(AK + (s)*4608 + r*HSTR + c8)*2, Kp + (size_t)((kb) + r)*DKK + c8); \
        cpa16(sb + (uint32_t)(AV + (s)*4608 + r*HSTR + c8)*2, Vp + (size_t)((kb) + r)*DKK + c8); \
    } \
} while (0)
    KV_LOAD(0, 0); cpa_commit();

    const int wr = wid * 16;
    const int q0 = qbase + wr + gid, q1 = q0 + 8;
    float m0 = -1e30f, m1 = -1e30f, l0 = 0.f, l1 = 0.f;
    float oacc[8][4];
#pragma unroll
    for (int nt = 0; nt < 8; nt++)
#pragma unroll
        for (int i = 0; i < 4; i++) oacc[nt][i] = 0.f;

    uint32_t qf[4][4];
    const int lrow = lane & 15, lcol = (lane >> 4) << 3;

    for (int kt = 0; kt < nk; kt++) {
        const int kbase = kt << 6;
        const int buf = kt & 1;
        asm volatile("cp.async.wait_group 0;");
        __syncthreads();
        if (kt == 0) {
#pragma unroll
            for (int ks = 0; ks < 4; ks++)
                ldm_x4(qf[ks][0], qf[ks][1], qf[ks][2], qf[ks][3],
                       sb + (uint32_t)(AQ + (wr + lrow)*HSTR + ks*16 + lcol)*2);
        }
        if (kt + 1 < nk) { KV_LOAD(kbase + 64, buf ^ 1); cpa_commit(); }

        const uint32_t kbuf = sb + (uint32_t)(AK + buf*4608)*2;
        const uint32_t vbuf = sb + (uint32_t)(AV + buf*4608)*2;

        float sacc[8][4];
#pragma unroll
        for (int nt = 0; nt < 8; nt++)
#pragma unroll
            for (int i = 0; i < 4; i++) sacc[nt][i] = 0.f;
#pragma unroll
        for (int ks = 0; ks < 4; ks++) {
#pragma unroll
            for (int nb = 0; nb < 4; nb++) {
                uint32_t r0, r1, r2, r3;
                ldm_x4(r0, r1, r2, r3,
                       kbuf + (uint32_t)((nb*16 + lrow)*HSTR + ks*16 + lcol)*2);
                mma_f16(sacc[nb*2],   qf[ks], r0, r2);
                mma_f16(sacc[nb*2+1], qf[ks], r1, r3);
            }
        }

#pragma unroll
        for (int nt = 0; nt < 8; nt++) {
            const int kc = kbase + nt*8 + tig*2;
            sacc[nt][0] = (kc   <= q0 && q0 < rowlen && kc   < collen) ? sacc[nt][0]*0.125f : -1e30f;
            sacc[nt][1] = (kc+1 <= q0 && q0 < rowlen && kc+1 < collen) ? sacc[nt][1]*0.125f : -1e30f;
            sacc[nt][2] = (kc   <= q1 && q1 < rowlen && kc   < collen) ? sacc[nt][2]*0.125f : -1e30f;
            sacc[nt][3] = (kc+1 <= q1 && q1 < rowlen && kc+1 < collen) ? sacc[nt][3]*0.125f : -1e30f;
        }

        float a0 = -1e30f, a1 = -1e30f;
#pragma unroll
        for (int nt = 0; nt < 8; nt++) {
            a0 = fmaxf(a0, fmaxf(sacc[nt][0], sacc[nt][1]));
            a1 = fmaxf(a1, fmaxf(sacc[nt][2], sacc[nt][3]));
        }
        a0 = fmaxf(a0, __shfl_xor_sync(0xffffffffu, a0, 1));
        a0 = fmaxf(a0, __shfl_xor_sync(0xffffffffu, a0, 2));
        a1 = fmaxf(a1, __shfl_xor_sync(0xffffffffu, a1, 1));
        a1 = fmaxf(a1, __shfl_xor_sync(0xffffffffu, a1, 2));

        const float mn0 = fmaxf(m0, a0), mn1 = fmaxf(m1, a1);
        const float sc0 = __expf(m0 - mn0), sc1 = __expf(m1 - mn1);
        l0 *= sc0; l1 *= sc1; m0 = mn0; m1 = mn1;
#pragma unroll
        for (int nt = 0; nt < 8; nt++) {
            oacc[nt][0] *= sc0; oacc[nt][1] *= sc0;
            oacc[nt][2] *= sc1; oacc[nt][3] *= sc1;
        }

        float rs0 = 0.f, rs1 = 0.f;
#pragma unroll
        for (int nt = 0; nt < 8; nt++) {
            sacc[nt][0] = __expf(sacc[nt][0] - mn0);
            sacc[nt][1] = __expf(sacc[nt][1] - mn0);
            sacc[nt][2] = __expf(sacc[nt][2] - mn1);
            sacc[nt][3] = __expf(sacc[nt][3] - mn1);
            rs0 += sacc[nt][0] + sacc[nt][1];
            rs1 += sacc[nt][2] + sacc[nt][3];
        }
        rs0 += __shfl_xor_sync(0xffffffffu, rs0, 1);
        rs0 += __shfl_xor_sync(0xffffffffu, rs0, 2);
        rs1 += __shfl_xor_sync(0xffffffffu, rs1, 1);
        rs1 += __shfl_xor_sync(0xffffffffu, rs1, 2);
        l0 += rs0; l1 += rs1;

#pragma unroll
        for (int ks = 0; ks < 4; ks++) {
            uint32_t pa[4];
            pa[0] = pack_f16x2(sacc[2*ks][0],   sacc[2*ks][1]);
            pa[1] = pack_f16x2(sacc[2*ks][2],   sacc[2*ks][3]);
            pa[2] = pack_f16x2(sacc[2*ks+1][0], sacc[2*ks+1][1]);
            pa[3] = pack_f16x2(sacc[2*ks+1][2], sacc[2*ks+1][3]);
#pragma unroll
            for (int db = 0; db < 4; db++) {
                uint32_t v0, v1, v2, v3;
                ldm_x4_t(v0, v1, v2, v3,
                         vbuf + (uint32_t)((ks*16 + lrow)*HSTR + db*16 + lcol)*2);
                mma_f16(oacc[db*2],   pa, v0, v1);
                mma_f16(oacc[db*2+1], pa, v2, v3);
            }
        }
    }
#undef KV_LOAD

    const float inv0 = (q0 < rowlen && l0 > 0.f) ? 1.f / l0 : 0.f;
    const float inv1 = (q1 < rowlen && l1 > 0.f) ? 1.f / l1 : 0.f;
#pragma unroll
    for (int nt = 0; nt < 8; nt++) {
        const int cc = nt*8 + tig*2;
        *(uint32_t*)(Hp + (size_t)q0*DD + cc) = pack_f16x2(oacc[nt][0]*inv0, oacc[nt][1]*inv0);
        *(uint32_t*)(Hp + (size_t)q1*DD + cc) = pack_f16x2(oacc[nt][2]*inv1, oacc[nt][3]*inv1);
    }
}

// ---------------------------------------------------------------------------
extern "C" void kernel_launch(void* const* d_in, const int* in_sizes, int n_in,
                              void* d_out, int out_size) {
    const float* in_Q = (const float*)d_in[0];
    const float* in_K = (const float*)d_in[1];
    const float* in_V = (const float*)d_in[2];
    const int*   rm   = (const int*)d_in[3];
    const int*   cm   = (const int*)d_in[4];
    const float* WQ = (const float*)d_in[5];  const float* bQ = (const float*)d_in[6];
    const float* WK = (const float*)d_in[7];  const float* bK = (const float*)d_in[8];
    const float* WV = (const float*)d_in[9];  const float* bV = (const float*)d_in[10];
    const float* WO = (const float*)d_in[11]; const float* bO = (const float*)d_in[12];
    float* out = (float*)d_out;

    cudaFuncSetAttribute(qkv_tc_kernel,   cudaFuncAttributeMaxDynamicSharedMemorySize, GEMM_SMEM_128);
    cudaFuncSetAttribute(oproj_tc_kernel, cudaFuncAttributeMaxDynamicSharedMemorySize, GEMM_SMEM_64);
    cudaFuncSetAttribute(attn_kernel,     cudaFuncAttributeMaxDynamicSharedMemorySize, ATTN_SMEM);

    prep_kernel<<<322, 256>>>(rm, cm, WQ, WK, WV, WO, bQ, bK, bV, in_Q, in_K, in_V);

    dim3 g1(32, 12);                   // M=4096/128, N=1536/128
    qkv_tc_kernel<<<g1, 256, GEMM_SMEM_128>>>();

    dim3 g2(1, 32, 16);                // 64-row q-tiles x (b*h), heavy-first
    attn_kernel<<<g2, 128, ATTN_SMEM>>>();

    dim3 g3(64, 4);                    // M=4096/64, N=512/128
    oproj_tc_kernel<<<g3, 256, GEMM_SMEM_64>>>(bO, out);
}